// round 11
// baseline (speedup 1.0000x reference)
#include <cuda_runtime.h>
#include <cuda_bf16.h>
#include <math.h>
#include <stdint.h>

// Problem constants
#define PP    2048
#define KK    10
#define LL    3
#define EE    256
#define HH    512
#define G4    2048      // 4*H
#define NPK   20480     // P*K
#define NENT  10000
#define NREL  200

// ---------------- scratch (static device globals; no allocs) ----------------
// NOTE: gate-dimension layout is INTERLEAVED everywhere: index = j*4 + gate
__device__ float g_W1[G4 * EE];          // tf32-rounded, rows interleaved
__device__ float g_W2[G4 * EE];          // tf32-rounded, rows interleaved
__device__ float g_biasc[G4];            // interleaved combined gate bias
__device__ float g_Wc[HH * HH];          // tf32-rounded (path_proj_w @ attn_out_w)
__device__ float g_bc2[HH];              // ppw@aob + ppb
__device__ float g_Wcv[HH * G4];         // tf32-rounded per-head fold: [i, h*512+e]
__device__ float g_bfin[HH];             // Wc@bv + bc2
__device__ float g_rel_gate[NREL * G4];  // interleaved cols
__device__ float g_ent_gate[NENT * G4];  // interleaved cols
__device__ float g_h0[NPK * HH];         // permuted layout, tf32-rounded
__device__ float g_h1[NPK * HH];         // permuted layout, tf32-rounded
__device__ float g_c[NPK * HH];          // permuted layout, exact fp32
__device__ float g_pemb[NPK * HH];       // PERMUTED layout, tf32-rounded
__device__ float g_qk[NPK * 2 * HH];     // ORIGINAL layout: q | k
__device__ float g_S[PP * G4];           // per-pair per-head weighted pemb sums
// tf32-rounded operand copies
__device__ float g_whr2[G4 * HH];        // w_hh rows interleaved + rounded
__device__ float g_aiw[2 * HH * HH];     // attn_in_w q,k part rounded
__device__ float g_entr[NENT * EE];
__device__ float g_relr[NREL * EE];

// length-sort state
__device__ int g_bins[4];
__device__ int g_off[4];
__device__ int g_cnt[3];                 // [0]=#len3, [1]=#len>=2, [2]=#len>=1
__device__ int g_perm[NPK];              // permuted -> original
__device__ int g_inv[NPK];               // original -> permuted

__device__ __forceinline__ float sigf(float x) { return 1.0f / (1.0f + expf(-x)); }
__device__ __forceinline__ float4 ld4(const float* p) { return *reinterpret_cast<const float4*>(p); }
__device__ __forceinline__ float tf32r(float x) {
    uint32_t r;
    asm("cvt.rna.tf32.f32 %0, %1;" : "=r"(r) : "f"(x));
    return __uint_as_float(r);
}
__device__ __forceinline__ uint32_t smem_u32(const void* p) {
    uint32_t a;
    asm("{ .reg .u64 tmp; cvta.to.shared.u64 tmp, %1; cvt.u32.u64 %0, tmp; }" : "=r"(a) : "l"(p));
    return a;
}
__device__ __forceinline__ void cp16(uint32_t dst, const void* src) {
    asm volatile("cp.async.cg.shared.global [%0], [%1], 16;" :: "r"(dst), "l"(src) : "memory");
}
__device__ __forceinline__ void mma_tf32(float* c, const uint32_t* a, const uint32_t* b) {
    asm volatile(
        "mma.sync.aligned.m16n8k8.row.col.f32.tf32.tf32.f32 "
        "{%0,%1,%2,%3}, {%4,%5,%6,%7}, {%8,%9}, {%0,%1,%2,%3};"
        : "+f"(c[0]), "+f"(c[1]), "+f"(c[2]), "+f"(c[3])
        : "r"(a[0]), "r"(a[1]), "r"(a[2]), "r"(a[3]), "r"(b[0]), "r"(b[1]));
}

#define MG_STRIDE 36
#define MG_BUF    18432

// ==================== generic mma.sync tf32 GEMM ============================
// C[M,N] = A[M,K] @ B[N,K]^T (+bias). ldb == Kd. cmap = C-row scatter ONLY.
#define MG_SMEM   (1024 + 4 * MG_BUF)
__global__ __launch_bounds__(256, 2) void mma_gemm(
    const float* __restrict__ A, int lda,
    const float* __restrict__ B,
    const float* __restrict__ bias,
    float* __restrict__ C, int ldc,
    int M, int Kd,
    const int* __restrict__ cntp,
    const int* __restrict__ cmap) {
    extern __shared__ char smem[];
    const int tid = threadIdx.x;
    const int wid = tid >> 5;
    const int lane = tid & 31;

    int Meff = M;
    if (cntp) { int cv = __ldg(cntp); Meff = (cv < M) ? cv : M; }
    const int m0 = blockIdx.y * 128;
    if (m0 >= Meff) return;
    const int n0 = blockIdx.x * 128;

    int* sPerm = reinterpret_cast<int*>(smem);
    float* bufA[2] = { reinterpret_cast<float*>(smem + 1024),
                       reinterpret_cast<float*>(smem + 1024 + 2 * MG_BUF) };
    float* bufB[2] = { reinterpret_cast<float*>(smem + 1024 + MG_BUF),
                       reinterpret_cast<float*>(smem + 1024 + 3 * MG_BUF) };
    uint32_t sbA[2] = { smem_u32(bufA[0]), smem_u32(bufA[1]) };
    uint32_t sbB[2] = { smem_u32(bufB[0]), smem_u32(bufB[1]) };

    if (cmap && tid < 128) sPerm[tid] = cmap[m0 + tid];
    __syncthreads();

    const int c4 = tid & 7;
    const float* srcA[4];
    const float* srcB[4];
    int dstOff[4];
#pragma unroll
    for (int i = 0; i < 4; i++) {
        int row = i * 32 + (tid >> 3);
        int r = m0 + row;
        if (r > Meff - 1) r = Meff - 1;
        srcA[i] = &A[(size_t)r * lda + c4 * 4];
        srcB[i] = &B[(size_t)(n0 + row) * Kd + c4 * 4];
        dstOff[i] = row * (MG_STRIDE * 4) + c4 * 16;
    }

    const int nch = Kd / 32;
    {
#pragma unroll
        for (int i = 0; i < 4; i++) {
            cp16(sbA[0] + dstOff[i], srcA[i]);
            cp16(sbB[0] + dstOff[i], srcB[i]);
        }
        asm volatile("cp.async.commit_group;" ::: "memory");
    }

    float acc[4][4][4];
#pragma unroll
    for (int mi = 0; mi < 4; mi++)
#pragma unroll
        for (int ni = 0; ni < 4; ni++)
#pragma unroll
            for (int q = 0; q < 4; q++) acc[mi][ni][q] = 0.f;

    const int g = lane >> 2, t = lane & 3;
    const int wm = wid >> 2, wn = wid & 3;

    for (int c = 0; c < nch; c++) {
        if (c + 1 < nch) {
            const int b = (c + 1) & 1;
            const int k0 = (c + 1) * 32;
#pragma unroll
            for (int i = 0; i < 4; i++) {
                cp16(sbA[b] + dstOff[i], srcA[i] + k0);
                cp16(sbB[b] + dstOff[i], srcB[i] + k0);
            }
            asm volatile("cp.async.commit_group;" ::: "memory");
            asm volatile("cp.async.wait_group 1;" ::: "memory");
        } else {
            asm volatile("cp.async.wait_group 0;" ::: "memory");
        }
        __syncthreads();

        const int b = c & 1;
        const uint32_t* As = reinterpret_cast<const uint32_t*>(bufA[b]);
        const uint32_t* Bs = reinterpret_cast<const uint32_t*>(bufB[b]);
#pragma unroll
        for (int k8 = 0; k8 < 4; k8++) {
            const int kc = k8 * 8 + t;
            uint32_t af[4][4];
#pragma unroll
            for (int mi = 0; mi < 4; mi++) {
                const uint32_t* ap = As + (wm * 64 + mi * 16 + g) * MG_STRIDE + kc;
                af[mi][0] = ap[0];
                af[mi][1] = ap[8 * MG_STRIDE];
                af[mi][2] = ap[4];
                af[mi][3] = ap[8 * MG_STRIDE + 4];
            }
            uint32_t bf[4][2];
#pragma unroll
            for (int ni = 0; ni < 4; ni++) {
                const uint32_t* bp = Bs + (wn * 32 + ni * 8 + g) * MG_STRIDE + kc;
                bf[ni][0] = bp[0];
                bf[ni][1] = bp[4];
            }
#pragma unroll
            for (int mi = 0; mi < 4; mi++)
#pragma unroll
                for (int ni = 0; ni < 4; ni++)
                    mma_tf32(acc[mi][ni], af[mi], bf[ni]);
        }
        __syncthreads();
    }

#pragma unroll
    for (int ni = 0; ni < 4; ni++) {
        const int col = n0 + wn * 32 + ni * 8 + 2 * t;
        float b0 = 0.f, b1 = 0.f;
        if (bias) { b0 = bias[col]; b1 = bias[col + 1]; }
#pragma unroll
        for (int mi = 0; mi < 4; mi++) {
            const int r0 = m0 + wm * 64 + mi * 16 + g;
            const int r1 = r0 + 8;
            if (r0 < Meff) {
                int ri = cmap ? sPerm[r0 - m0] : r0;
                float2 v = make_float2(acc[mi][ni][0] + b0, acc[mi][ni][1] + b1);
                *reinterpret_cast<float2*>(&C[(size_t)ri * ldc + col]) = v;
            }
            if (r1 < Meff) {
                int ri = cmap ? sPerm[r1 - m0] : r1;
                float2 v = make_float2(acc[mi][ni][2] + b0, acc[mi][ni][3] + b1);
                *reinterpret_cast<float2*>(&C[(size_t)ri * ldc + col]) = v;
            }
        }
    }
}

// ============ LSTM gates GEMM with FUSED cell epilogue ======================
// A = h_prev (permuted, tf32), B = g_whr2 (interleaved rows, K=512).
// Epilogue: lane pairs swap accumulators so each lane owns all 4 gates of one
// (row, j); applies rel/ent/bias gathers and the LSTM cell; writes c/h/pemb.
#define MGL_SMEM  (2048 + 4 * MG_BUF)
__global__ __launch_bounds__(256, 2) void mma_gemm_lstm(
    const float* __restrict__ A,
    float* __restrict__ h_next,
    const int* __restrict__ rel_idx, const int* __restrict__ ent_idx,
    const int* __restrict__ path_lens, const int* __restrict__ perm,
    const int* __restrict__ cntp, int tstep) {
    extern __shared__ char smem[];
    const int tid = threadIdx.x;
    const int wid = tid >> 5;
    const int lane = tid & 31;

    const int Meff = __ldg(cntp);
    const int m0 = blockIdx.y * 128;
    if (m0 >= Meff) return;
    const int n0 = blockIdx.x * 128;

    int* sRel = reinterpret_cast<int*>(smem);
    int* sEnt = reinterpret_cast<int*>(smem + 512);
    int* sLen = reinterpret_cast<int*>(smem + 1024);
    float* bufA[2] = { reinterpret_cast<float*>(smem + 2048),
                       reinterpret_cast<float*>(smem + 2048 + 2 * MG_BUF) };
    float* bufB[2] = { reinterpret_cast<float*>(smem + 2048 + MG_BUF),
                       reinterpret_cast<float*>(smem + 2048 + 3 * MG_BUF) };
    uint32_t sbA[2] = { smem_u32(bufA[0]), smem_u32(bufA[1]) };
    uint32_t sbB[2] = { smem_u32(bufB[0]), smem_u32(bufB[1]) };

    if (tid < 128) {
        int r = m0 + tid;
        if (r > Meff - 1) r = Meff - 1;
        int orig = perm[r];
        sRel[tid] = rel_idx[orig * LL + tstep];
        sEnt[tid] = ent_idx[orig * LL + tstep];
        sLen[tid] = path_lens[orig];
    }

    const int c4 = tid & 7;
    const float* srcA[4];
    const float* srcB[4];
    int dstOff[4];
#pragma unroll
    for (int i = 0; i < 4; i++) {
        int row = i * 32 + (tid >> 3);
        int r = m0 + row;
        if (r > Meff - 1) r = Meff - 1;
        srcA[i] = &A[(size_t)r * HH + c4 * 4];
        srcB[i] = &g_whr2[(size_t)(n0 + row) * HH + c4 * 4];
        dstOff[i] = row * (MG_STRIDE * 4) + c4 * 16;
    }

    const int nch = HH / 32;
    {
#pragma unroll
        for (int i = 0; i < 4; i++) {
            cp16(sbA[0] + dstOff[i], srcA[i]);
            cp16(sbB[0] + dstOff[i], srcB[i]);
        }
        asm volatile("cp.async.commit_group;" ::: "memory");
    }

    float acc[4][4][4];
#pragma unroll
    for (int mi = 0; mi < 4; mi++)
#pragma unroll
        for (int ni = 0; ni < 4; ni++)
#pragma unroll
            for (int q = 0; q < 4; q++) acc[mi][ni][q] = 0.f;

    const int lg = lane >> 2, lt = lane & 3;
    const int wm = wid >> 2, wn = wid & 3;

    for (int c = 0; c < nch; c++) {
        if (c + 1 < nch) {
            const int b = (c + 1) & 1;
            const int k0 = (c + 1) * 32;
#pragma unroll
            for (int i = 0; i < 4; i++) {
                cp16(sbA[b] + dstOff[i], srcA[i] + k0);
                cp16(sbB[b] + dstOff[i], srcB[i] + k0);
            }
            asm volatile("cp.async.commit_group;" ::: "memory");
            asm volatile("cp.async.wait_group 1;" ::: "memory");
        } else {
            asm volatile("cp.async.wait_group 0;" ::: "memory");
        }
        __syncthreads();

        const int b = c & 1;
        const uint32_t* As = reinterpret_cast<const uint32_t*>(bufA[b]);
        const uint32_t* Bs = reinterpret_cast<const uint32_t*>(bufB[b]);
#pragma unroll
        for (int k8 = 0; k8 < 4; k8++) {
            const int kc = k8 * 8 + lt;
            uint32_t af[4][4];
#pragma unroll
            for (int mi = 0; mi < 4; mi++) {
                const uint32_t* ap = As + (wm * 64 + mi * 16 + lg) * MG_STRIDE + kc;
                af[mi][0] = ap[0];
                af[mi][1] = ap[8 * MG_STRIDE];
                af[mi][2] = ap[4];
                af[mi][3] = ap[8 * MG_STRIDE + 4];
            }
            uint32_t bf[4][2];
#pragma unroll
            for (int ni = 0; ni < 4; ni++) {
                const uint32_t* bp = Bs + (wn * 32 + ni * 8 + lg) * MG_STRIDE + kc;
                bf[ni][0] = bp[0];
                bf[ni][1] = bp[4];
            }
#pragma unroll
            for (int mi = 0; mi < 4; mi++)
#pragma unroll
                for (int ni = 0; ni < 4; ni++)
                    mma_tf32(acc[mi][ni], af[mi], bf[ni]);
        }
        __syncthreads();
    }

    // ----- fused cell epilogue -----
    // cols (CTA-local) = wn*32 + ni*8 + 2lt (+1); interleaved: gate = col&3,
    // j = col>>2. Lane pair (lt, lt^1) jointly holds gates i,f,g,o of one j.
    const bool odd = (lt & 1);
#pragma unroll
    for (int ni = 0; ni < 4; ni++) {
        const int jg = blockIdx.x * 32 + wn * 8 + ni * 2 + (lt >> 1);
        const float4 bc = ld4(&g_biasc[jg * 4]);
#pragma unroll
        for (int mi = 0; mi < 4; mi++) {
            float ex0 = __shfl_xor_sync(0xffffffffu, acc[mi][ni][0], 1);
            float ex1 = __shfl_xor_sync(0xffffffffu, acc[mi][ni][1], 1);
            float ex2 = __shfl_xor_sync(0xffffffffu, acc[mi][ni][2], 1);
            float ex3 = __shfl_xor_sync(0xffffffffu, acc[mi][ni][3], 1);
            // even lane -> row r0 (gates i,f own; g,o from partner)
            // odd lane  -> row r1 (gates g,o own; i,f from partner)
            float vi = odd ? ex2 : acc[mi][ni][0];
            float vf = odd ? ex3 : acc[mi][ni][1];
            float vg = odd ? acc[mi][ni][2] : ex0;
            float vo = odd ? acc[mi][ni][3] : ex1;
            const int row_l = wm * 64 + mi * 16 + lg + (odd ? 8 : 0);
            const int row = m0 + row_l;
            if (row < Meff) {
                const int ridx = sRel[row_l];
                const int eidx = sEnt[row_l];
                float4 rg = ld4(&g_rel_gate[(size_t)ridx * G4 + jg * 4]);
                float4 eg = ld4(&g_ent_gate[(size_t)eidx * G4 + jg * 4]);
                size_t off = (size_t)row * HH + jg;
                float cold = g_c[off];
                float gi = vi + rg.x + eg.x + bc.x;
                float gf = vf + rg.y + eg.y + bc.y;
                float gG = vg + rg.z + eg.z + bc.z;
                float gO = vo + rg.w + eg.w + bc.w;
                float cn = sigf(gf) * cold + sigf(gi) * tanhf(gG);
                float hn = tf32r(sigf(gO) * tanhf(cn));
                g_c[off] = cn;
                h_next[off] = hn;
                if (sLen[row_l] == tstep + 1) g_pemb[off] = hn;
            }
        }
    }
}

// ---------------- tf32 rounding copy ---------------------------------------
__global__ void round_tf32_kernel(const float* __restrict__ in, float* __restrict__ out, int n4) {
    int i = blockIdx.x * blockDim.x + threadIdx.x;
    if (i < n4) {
        float4 v = ld4(&in[i * 4]);
        v.x = tf32r(v.x); v.y = tf32r(v.y); v.z = tf32r(v.z); v.w = tf32r(v.w);
        *reinterpret_cast<float4*>(&out[i * 4]) = v;
    }
}

// ---------------- w_hh reorder+round: row n=j*4+gate <- w_hh[gate*512+j] ----
__global__ void reorder_whr_kernel(const float* __restrict__ w_hh) {
    int n = blockIdx.x;
    int src = (n & 3) * HH + (n >> 2);
    const float4* s = reinterpret_cast<const float4*>(&w_hh[(size_t)src * HH]);
    float4* d = reinterpret_cast<float4*>(&g_whr2[(size_t)n * HH]);
    int i = threadIdx.x;                 // 128 threads, HH/4 = 128
    float4 v = s[i];
    v.x = tf32r(v.x); v.y = tf32r(v.y); v.z = tf32r(v.z); v.w = tf32r(v.w);
    d[i] = v;
}

// ================= small fp32 GEMM (precompute, NN form) ====================
#define BM 128
#define BN 64
#define BK 16
#define TPB 256

template <bool ROUND, bool ROWMAP>
__global__ void gemm_nn_small(const float* __restrict__ A, const float* __restrict__ B,
                              float* __restrict__ C,
                              int M, int N, int Kd, int lda, int ldb, int ldc) {
    __shared__ float shA[BK][BM + 4];
    __shared__ float shB[BK][BN + 2];
    const int m0 = blockIdx.y * BM;
    const int n0 = blockIdx.x * BN;
    const int tid = threadIdx.x;
    const int jj = tid & 15;
    const int rg = tid >> 4;
    const int r0 = rg * 8;

    float acc[8][4];
#pragma unroll
    for (int i = 0; i < 8; i++)
#pragma unroll
        for (int q = 0; q < 4; q++) acc[i][q] = 0.0f;

    const int a_row = tid >> 2;
    const int a_k4  = (tid & 3) * 4;

    for (int k0 = 0; k0 < Kd; k0 += BK) {
#pragma unroll
        for (int hhalf = 0; hhalf < 2; hhalf++) {
            int r = a_row + hhalf * 64;
            int m = m0 + r;
            float4 v = make_float4(0.f, 0.f, 0.f, 0.f);
            if (m < M) v = ld4(&A[(size_t)m * lda + k0 + a_k4]);
            shA[a_k4 + 0][r] = v.x;
            shA[a_k4 + 1][r] = v.y;
            shA[a_k4 + 2][r] = v.z;
            shA[a_k4 + 3][r] = v.w;
        }
        {
            int kk2 = tid >> 4;
            int cc  = (tid & 15) * 4;
            float4 v = ld4(&B[(size_t)(k0 + kk2) * ldb + n0 + cc]);
            shB[kk2][cc + 0] = v.x;
            shB[kk2][cc + 1] = v.y;
            shB[kk2][cc + 2] = v.z;
            shB[kk2][cc + 3] = v.w;
        }
        __syncthreads();
#pragma unroll
        for (int k = 0; k < BK; k++) {
            float4 a01 = ld4(&shA[k][r0]);
            float4 a23 = ld4(&shA[k][r0 + 4]);
            float b0 = shB[k][jj], b1 = shB[k][jj + 16], b2 = shB[k][jj + 32], b3 = shB[k][jj + 48];
            float a[8] = {a01.x, a01.y, a01.z, a01.w, a23.x, a23.y, a23.z, a23.w};
#pragma unroll
            for (int i = 0; i < 8; i++) {
                acc[i][0] += a[i] * b0;
                acc[i][1] += a[i] * b1;
                acc[i][2] += a[i] * b2;
                acc[i][3] += a[i] * b3;
            }
        }
        __syncthreads();
    }
#pragma unroll
    for (int i = 0; i < 8; i++) {
        int m = m0 + r0 + i;
        if (m < M) {
            int mo = ROWMAP ? (((m & 511) << 2) | (m >> 9)) : m;   // gate*512+j -> j*4+gate
            float* crow = &C[(size_t)mo * ldc + n0];
            if (ROUND) {
                crow[jj]      = tf32r(acc[i][0]);
                crow[jj + 16] = tf32r(acc[i][1]);
                crow[jj + 32] = tf32r(acc[i][2]);
                crow[jj + 48] = tf32r(acc[i][3]);
            } else {
                crow[jj]      = acc[i][0];
                crow[jj + 16] = acc[i][1];
                crow[jj + 32] = acc[i][2];
                crow[jj + 48] = acc[i][3];
            }
        }
    }
}

// ---------------- combined gate bias (writes interleaved) ------------------
__global__ void biasc_kernel(const float* __restrict__ kg_proj_b, const float* __restrict__ w_ih,
                             const float* __restrict__ b_ih, const float* __restrict__ b_hh) {
    int g = blockIdx.x;                  // row of w_ih = gate*512+j
    float s = 0.f;
    const float* row = &w_ih[(size_t)g * (2 * HH)];
    for (int h = threadIdx.x; h < HH; h += 128) s += kg_proj_b[h] * (row[h] + row[HH + h]);
    __shared__ float red[128];
    red[threadIdx.x] = s;
    __syncthreads();
    for (int off = 64; off > 0; off >>= 1) {
        if (threadIdx.x < off) red[threadIdx.x] += red[threadIdx.x + off];
        __syncthreads();
    }
    if (threadIdx.x == 0) {
        int idx = ((g & 511) << 2) | (g >> 9);
        g_biasc[idx] = red[0] + b_ih[g] + b_hh[g];
    }
}

// ---------------- folded output biases --------------------------------------
__global__ void biasfold_kernel(const float* __restrict__ ppw, const float* __restrict__ aob,
                                const float* __restrict__ ppb) {
    int i = blockIdx.x;
    float s = 0.f;
    const float* row = &ppw[(size_t)i * HH];
    for (int jx = threadIdx.x; jx < HH; jx += 128) s += row[jx] * aob[jx];
    __shared__ float red[128];
    red[threadIdx.x] = s;
    __syncthreads();
    for (int off = 64; off > 0; off >>= 1) {
        if (threadIdx.x < off) red[threadIdx.x] += red[threadIdx.x + off];
        __syncthreads();
    }
    if (threadIdx.x == 0) g_bc2[i] = red[0] + ppb[i];
}

// bfin = Wc @ bv + bc2
__global__ void biasfold2_kernel(const float* __restrict__ bv) {
    int i = blockIdx.x;
    float s = 0.f;
    const float* row = &g_Wc[(size_t)i * HH];
    for (int jx = threadIdx.x; jx < HH; jx += 128) s += row[jx] * bv[jx];
    __shared__ float red[128];
    red[threadIdx.x] = s;
    __syncthreads();
    for (int off = 64; off > 0; off >>= 1) {
        if (threadIdx.x < off) red[threadIdx.x] += red[threadIdx.x + off];
        __syncthreads();
    }
    if (threadIdx.x == 0) g_bfin[i] = red[0] + g_bc2[i];
}

// ---------------- counting sort by path length (descending) ----------------
__global__ void sort_init() {
    if (threadIdx.x < 4) g_bins[threadIdx.x] = 0;
}
__global__ void sort_count(const int* __restrict__ lens) {
    int n = blockIdx.x * blockDim.x + threadIdx.x;
    if (n < NPK) {
        int l = lens[n]; l = max(0, min(3, l));
        atomicAdd(&g_bins[3 - l], 1);
    }
}
__global__ void sort_prefix() {
    int c0 = g_bins[0], c1 = g_bins[1], c2 = g_bins[2];
    g_off[0] = 0; g_off[1] = c0; g_off[2] = c0 + c1; g_off[3] = c0 + c1 + c2;
    g_cnt[0] = c0; g_cnt[1] = c0 + c1; g_cnt[2] = c0 + c1 + c2;
}
__global__ void sort_scatter(const int* __restrict__ lens) {
    int n = blockIdx.x * blockDim.x + threadIdx.x;
    if (n < NPK) {
        int l = lens[n]; l = max(0, min(3, l));
        int pos = atomicAdd(&g_off[3 - l], 1);
        g_perm[pos] = n;
        g_inv[n] = pos;
    }
}

// ---------------- LSTM step 0 (h=c=0), permuted layout, interleaved tables -
__global__ void step0_kernel(const int* __restrict__ rel_idx, const int* __restrict__ ent_idx,
                             const int* __restrict__ path_lens, const int* __restrict__ perm) {
    int n = blockIdx.x;
    int orig = perm[n];
    int ridx = rel_idx[orig * LL + 0];
    int eidx = ent_idx[orig * LL + 0];
    int len  = path_lens[orig];
    const float4* rg4 = reinterpret_cast<const float4*>(&g_rel_gate[(size_t)ridx * G4]);
    const float4* eg4 = reinterpret_cast<const float4*>(&g_ent_gate[(size_t)eidx * G4]);
    const float4* bc4 = reinterpret_cast<const float4*>(g_biasc);

#pragma unroll
    for (int it = 0; it < 4; it++) {
        int j = threadIdx.x + it * 128;
        float4 r = rg4[j], e = eg4[j], b = bc4[j];
        float gi = r.x + e.x + b.x;
        float gg = r.z + e.z + b.z;
        float go = r.w + e.w + b.w;
        float cn = sigf(gi) * tanhf(gg);
        float hn = tf32r(sigf(go) * tanhf(cn));
        size_t off = (size_t)n * HH + j;
        g_h0[off] = hn;
        g_c[off]  = cn;
        if (len == 1) g_pemb[off] = hn;
    }
}

// qk rows for len==0 paths: pemb row = 0 -> qk row = bias (orig layout)
__global__ void qk_fill_kernel(const float* __restrict__ bias,
                               const int* __restrict__ perm, const int* __restrict__ cntp) {
    int m = blockIdx.x;
    if (m < __ldg(cntp)) return;
    int orig = perm[m];
    float4* row = reinterpret_cast<float4*>(&g_qk[(size_t)orig * (2 * HH)]);
    const float4* b4 = reinterpret_cast<const float4*>(bias);
    for (int i = threadIdx.x; i < (2 * HH) / 4; i += blockDim.x) row[i] = b4[i];
}

// -------- attention: scores/softmax/col-mean, emit per-head pemb sums S ----
__global__ void attn2_kernel(const int* __restrict__ cntp) {
    extern __shared__ float dyn[];
    float* sq = dyn;                 // [10][512]
    float* sk = dyn + 10 * HH;       // [10][512]
    float* sp = dyn + 20 * HH;       // [10][512] gathered pemb
    __shared__ float sc[4][KK][KK + 2];
    __shared__ float wcol[4][KK];
    __shared__ int spos[KK];

    int p = blockIdx.x;
    int tid = threadIdx.x;           // 256
    const int cnt2 = __ldg(cntp);

    if (tid < KK) spos[tid] = g_inv[p * KK + tid];
    __syncthreads();

    for (int i = tid; i < KK * HH; i += 256) {
        int a = i >> 9, d = i & 511;
        size_t base = (size_t)(p * KK + a) * (2 * HH);
        sq[a * HH + d] = g_qk[base + d];
        sk[a * HH + d] = g_qk[base + HH + d];
        int pos = spos[a];
        sp[a * HH + d] = (pos < cnt2) ? g_pemb[(size_t)pos * HH + d] : 0.f;
    }
    __syncthreads();

    for (int item = tid; item < 4 * KK * KK; item += 256) {
        int h = item / (KK * KK);
        int rem = item % (KK * KK);
        int a = rem / KK, b = rem % KK;
        float s = 0.f;
        const float* qa = &sq[a * HH + h * 128];
        const float* kb = &sk[b * HH + h * 128];
#pragma unroll 8
        for (int d = 0; d < 128; d++) s += qa[d] * kb[d];
        sc[h][a][b] = s * 0.08838834764831845f;
    }
    __syncthreads();

    if (tid < 4 * KK) {
        int h = tid / KK, a = tid % KK;
        float mx = -1e30f;
        for (int b = 0; b < KK; b++) mx = fmaxf(mx, sc[h][a][b]);
        float e[KK], sum = 0.f;
        for (int b = 0; b < KK; b++) { e[b] = expf(sc[h][a][b] - mx); sum += e[b]; }
        float inv = 1.f / sum;
        for (int b = 0; b < KK; b++) sc[h][a][b] = e[b] * inv;
    }
    __syncthreads();
    if (tid < 4 * KK) {
        int h = tid / KK, b = tid % KK;
        float s = 0.f;
        for (int a = 0; a < KK; a++) s += sc[h][a][b];
        wcol[h][b] = s * 0.1f;
    }
    __syncthreads();

    for (int i = tid; i < G4; i += 256) {
        int h = i >> 9, d = i & 511;
        float s = 0.f;
#pragma unroll
        for (int b = 0; b < KK; b++) s += wcol[h][b] * sp[b * HH + d];
        g_S[(size_t)p * G4 + i] = tf32r(s);
    }
}

// ---------------- launch --------------------------------------------------
extern "C" void kernel_launch(void* const* d_in, const int* in_sizes, int n_in,
                              void* d_out, int out_size) {
    const int*   rel_idx     = (const int*)d_in[0];
    const int*   ent_idx     = (const int*)d_in[1];
    const int*   path_lens   = (const int*)d_in[2];
    const float* rel_table   = (const float*)d_in[3];
    const float* ent_table   = (const float*)d_in[4];
    const float* kg_proj_w   = (const float*)d_in[5];
    const float* kg_proj_b   = (const float*)d_in[6];
    const float* w_ih        = (const float*)d_in[7];
    const float* w_hh        = (const float*)d_in[8];
    const float* b_ih        = (const float*)d_in[9];
    const float* b_hh        = (const float*)d_in[10];
    const float* attn_in_w   = (const float*)d_in[11];
    const float* attn_in_b   = (const float*)d_in[12];
    const float* attn_out_w  = (const float*)d_in[13];
    const float* attn_out_b  = (const float*)d_in[14];
    const float* path_proj_w = (const float*)d_in[15];
    const float* path_proj_b = (const float*)d_in[16];
    float* out = (float*)d_out;

    float *pW1, *pW2, *pRel, *pEnt, *pH0, *pH1, *pPemb, *pQk, *pS, *pWc, *pWcv;
    float *pAiw, *pEntr, *pRelr;
    int *pPerm, *pCnt;
    cudaGetSymbolAddress((void**)&pW1, g_W1);
    cudaGetSymbolAddress((void**)&pW2, g_W2);
    cudaGetSymbolAddress((void**)&pRel, g_rel_gate);
    cudaGetSymbolAddress((void**)&pEnt, g_ent_gate);
    cudaGetSymbolAddress((void**)&pH0, g_h0);
    cudaGetSymbolAddress((void**)&pH1, g_h1);
    cudaGetSymbolAddress((void**)&pPemb, g_pemb);
    cudaGetSymbolAddress((void**)&pQk, g_qk);
    cudaGetSymbolAddress((void**)&pS, g_S);
    cudaGetSymbolAddress((void**)&pWc, g_Wc);
    cudaGetSymbolAddress((void**)&pWcv, g_Wcv);
    cudaGetSymbolAddress((void**)&pAiw, g_aiw);
    cudaGetSymbolAddress((void**)&pEntr, g_entr);
    cudaGetSymbolAddress((void**)&pRelr, g_relr);
    cudaGetSymbolAddress((void**)&pPerm, g_perm);
    cudaGetSymbolAddress((void**)&pCnt, g_cnt);

    cudaFuncSetAttribute(mma_gemm, cudaFuncAttributeMaxDynamicSharedMemorySize, MG_SMEM);
    cudaFuncSetAttribute(mma_gemm_lstm, cudaFuncAttributeMaxDynamicSharedMemorySize, MGL_SMEM);
    cudaFuncSetAttribute(attn2_kernel, cudaFuncAttributeMaxDynamicSharedMemorySize, 30 * HH * 4);

    // --- precompute (ordered so launch #5 = the big ent mma_gemm) ---
    gemm_nn_small<true, true><<<dim3(EE / BN, G4 / BM), TPB>>>(w_ih,      kg_proj_w, pW1,
                                                               G4, EE, HH, 2 * HH, EE, EE);
    gemm_nn_small<true, true><<<dim3(EE / BN, G4 / BM), TPB>>>(w_ih + HH, kg_proj_w, pW2,
                                                               G4, EE, HH, 2 * HH, EE, EE);
    round_tf32_kernel<<<(NENT * EE / 4 + 255) / 256, 256>>>(ent_table, pEntr, NENT * EE / 4);
    round_tf32_kernel<<<(NREL * EE / 4 + 255) / 256, 256>>>(rel_table, pRelr, NREL * EE / 4);
    round_tf32_kernel<<<(2 * HH * HH / 4 + 255) / 256, 256>>>(attn_in_w, pAiw, 2 * HH * HH / 4);
    // per-entity gate tables (interleaved cols via interleaved W rows)
    mma_gemm<<<dim3(G4 / 128, (NENT + 127) / 128), 256, MG_SMEM>>>(
        pEntr, EE, pW2, nullptr, pEnt, G4, NENT, EE, nullptr, nullptr);
    mma_gemm<<<dim3(G4 / 128, (NREL + 127) / 128), 256, MG_SMEM>>>(
        pRelr, EE, pW1, nullptr, pRel, G4, NREL, EE, nullptr, nullptr);

    // --- counting sort by path length (descending) + inverse perm ---
    sort_init<<<1, 32>>>();
    sort_count<<<(NPK + 255) / 256, 256>>>(path_lens);
    sort_prefix<<<1, 1>>>();
    sort_scatter<<<(NPK + 255) / 256, 256>>>(path_lens);

    reorder_whr_kernel<<<G4, 128>>>(w_hh);
    biasc_kernel<<<G4, 128>>>(kg_proj_b, w_ih, b_ih, b_hh);

    // folded output: Wc = ppw@aow ; Wcv per-head ; biases
    gemm_nn_small<true, false><<<dim3(HH / BN, HH / BM), TPB>>>(path_proj_w, attn_out_w, pWc,
                                                                HH, HH, HH, HH, HH, HH);
    biasfold_kernel<<<HH, 128>>>(path_proj_w, attn_out_b, path_proj_b);
    biasfold2_kernel<<<HH, 128>>>(attn_in_b + 2 * HH);
    for (int h = 0; h < 4; h++) {
        gemm_nn_small<true, false><<<dim3(HH / BN, HH / BM), TPB>>>(
            pWc + h * 128, attn_in_w + (size_t)(2 * HH + h * 128) * HH, pWcv + h * HH,
            HH, HH, 128, HH, HH, G4);
    }

    // --- LSTM: step0 gather; steps 1,2 fused GEMM+cell on compacted prefix ---
    step0_kernel<<<NPK, 128>>>(rel_idx, ent_idx, path_lens, pPerm);
    mma_gemm_lstm<<<dim3(G4 / 128, NPK / 128), 256, MGL_SMEM>>>(
        pH0, pH1, rel_idx, ent_idx, path_lens, pPerm, pCnt + 1, 1);
    mma_gemm_lstm<<<dim3(G4 / 128, NPK / 128), 256, MGL_SMEM>>>(
        pH1, pH0, rel_idx, ent_idx, path_lens, pPerm, pCnt + 0, 2);

    // --- QK projection (compacted pemb rows; scatter to original layout) ---
    mma_gemm<<<dim3(2 * HH / 128, NPK / 128), 256, MG_SMEM>>>(
        pPemb, HH, pAiw, attn_in_b, pQk, 2 * HH, NPK, HH, pCnt + 2, pPerm);
    qk_fill_kernel<<<NPK, 128>>>(attn_in_b, pPerm, pCnt + 2);

    // --- attention -> per-head weighted pemb sums S ---
    attn2_kernel<<<PP, 256, 30 * HH * 4>>>(pCnt + 2);

    // --- single folded output GEMM: out = S @ Wcv^T + bfin ---
    float* pBfin;
    cudaGetSymbolAddress((void**)&pBfin, g_bfin);
    mma_gemm<<<dim3(HH / 128, PP / 128), 256, MG_SMEM>>>(
        pS, G4, pWcv, pBfin, out, HH, PP, G4, nullptr, nullptr);
}

// round 16
// speedup vs baseline: 1.1036x; 1.1036x over previous
#include <cuda_runtime.h>
#include <cuda_bf16.h>
#include <math.h>
#include <stdint.h>

// Problem constants
#define PP    2048
#define KK    10
#define LL    3
#define EE    256
#define HH    512
#define G4    2048      // 4*H
#define NPK   20480     // P*K
#define NENT  10000
#define NREL  200

// ---------------- scratch (static device globals; no allocs) ----------------
// NOTE: gate-dimension layout is INTERLEAVED everywhere: index = j*4 + gate
__device__ float g_W1[G4 * EE];          // tf32-rounded, rows interleaved
__device__ float g_W2[G4 * EE];          // tf32-rounded, rows interleaved
__device__ float g_biasc[G4];            // interleaved combined gate bias
__device__ float g_Wc[HH * HH];          // tf32-rounded (path_proj_w @ attn_out_w)
__device__ float g_bc2[HH];              // ppw@aob + ppb
__device__ float g_rel_gate[NREL * G4];  // interleaved cols
__device__ float g_ent_gate[NENT * G4];  // interleaved cols
__device__ float g_h0[NPK * HH];         // permuted layout, tf32-rounded
__device__ float g_h1[NPK * HH];         // permuted layout, tf32-rounded
__device__ float g_c[NPK * HH];          // permuted layout, exact fp32
__device__ float g_pemb[NPK * HH];       // PERMUTED layout, tf32-rounded
__device__ float g_qkv[NPK * 3 * HH];    // ORIGINAL layout: q | k | v
__device__ float g_ctxmean[PP * HH];     // tf32-rounded
// tf32-rounded operand copies
__device__ float g_whr2[G4 * HH];        // w_hh rows interleaved + rounded
__device__ float g_aiw[3 * HH * HH];     // attn_in_w rounded
__device__ float g_entr[NENT * EE];
__device__ float g_relr[NREL * EE];

// length-sort state
__device__ int g_bins[4];
__device__ int g_off[4];
__device__ int g_cnt[3];                 // [0]=#len3, [1]=#len>=2, [2]=#len>=1
__device__ int g_perm[NPK];              // permuted -> original

__device__ __forceinline__ float sigf(float x) { return 1.0f / (1.0f + expf(-x)); }
__device__ __forceinline__ float4 ld4(const float* p) { return *reinterpret_cast<const float4*>(p); }
__device__ __forceinline__ float tf32r(float x) {
    uint32_t r;
    asm("cvt.rna.tf32.f32 %0, %1;" : "=r"(r) : "f"(x));
    return __uint_as_float(r);
}
__device__ __forceinline__ uint32_t smem_u32(const void* p) {
    uint32_t a;
    asm("{ .reg .u64 tmp; cvta.to.shared.u64 tmp, %1; cvt.u32.u64 %0, tmp; }" : "=r"(a) : "l"(p));
    return a;
}
__device__ __forceinline__ void cp16(uint32_t dst, const void* src) {
    asm volatile("cp.async.cg.shared.global [%0], [%1], 16;" :: "r"(dst), "l"(src) : "memory");
}
__device__ __forceinline__ void mma_tf32(float* c, const uint32_t* a, const uint32_t* b) {
    asm volatile(
        "mma.sync.aligned.m16n8k8.row.col.f32.tf32.tf32.f32 "
        "{%0,%1,%2,%3}, {%4,%5,%6,%7}, {%8,%9}, {%0,%1,%2,%3};"
        : "+f"(c[0]), "+f"(c[1]), "+f"(c[2]), "+f"(c[3])
        : "r"(a[0]), "r"(a[1]), "r"(a[2]), "r"(a[3]), "r"(b[0]), "r"(b[1]));
}

#define MG_STRIDE 36
#define MG_BUF    18432

// ==================== generic mma.sync tf32 GEMM ============================
// C[M,N] = A[M,K] @ B[N,K]^T (+bias). ldb == Kd. cmap = C-row scatter ONLY.
#define MG_SMEM   (1024 + 4 * MG_BUF)
__global__ __launch_bounds__(256, 2) void mma_gemm(
    const float* __restrict__ A, int lda,
    const float* __restrict__ B,
    const float* __restrict__ bias,
    float* __restrict__ C, int ldc,
    int M, int Kd,
    const int* __restrict__ cntp,
    const int* __restrict__ cmap) {
    extern __shared__ char smem[];
    const int tid = threadIdx.x;
    const int wid = tid >> 5;
    const int lane = tid & 31;

    int Meff = M;
    if (cntp) { int cv = __ldg(cntp); Meff = (cv < M) ? cv : M; }
    const int m0 = blockIdx.y * 128;
    if (m0 >= Meff) return;
    const int n0 = blockIdx.x * 128;

    int* sPerm = reinterpret_cast<int*>(smem);
    float* bufA[2] = { reinterpret_cast<float*>(smem + 1024),
                       reinterpret_cast<float*>(smem + 1024 + 2 * MG_BUF) };
    float* bufB[2] = { reinterpret_cast<float*>(smem + 1024 + MG_BUF),
                       reinterpret_cast<float*>(smem + 1024 + 3 * MG_BUF) };
    uint32_t sbA[2] = { smem_u32(bufA[0]), smem_u32(bufA[1]) };
    uint32_t sbB[2] = { smem_u32(bufB[0]), smem_u32(bufB[1]) };

    if (cmap && tid < 128) sPerm[tid] = cmap[m0 + tid];
    __syncthreads();

    const int c4 = tid & 7;
    const float* srcA[4];
    const float* srcB[4];
    int dstOff[4];
#pragma unroll
    for (int i = 0; i < 4; i++) {
        int row = i * 32 + (tid >> 3);
        int r = m0 + row;
        if (r > Meff - 1) r = Meff - 1;
        srcA[i] = &A[(size_t)r * lda + c4 * 4];
        srcB[i] = &B[(size_t)(n0 + row) * Kd + c4 * 4];
        dstOff[i] = row * (MG_STRIDE * 4) + c4 * 16;
    }

    const int nch = Kd / 32;
    {
#pragma unroll
        for (int i = 0; i < 4; i++) {
            cp16(sbA[0] + dstOff[i], srcA[i]);
            cp16(sbB[0] + dstOff[i], srcB[i]);
        }
        asm volatile("cp.async.commit_group;" ::: "memory");
    }

    float acc[4][4][4];
#pragma unroll
    for (int mi = 0; mi < 4; mi++)
#pragma unroll
        for (int ni = 0; ni < 4; ni++)
#pragma unroll
            for (int q = 0; q < 4; q++) acc[mi][ni][q] = 0.f;

    const int g = lane >> 2, t = lane & 3;
    const int wm = wid >> 2, wn = wid & 3;

    for (int c = 0; c < nch; c++) {
        if (c + 1 < nch) {
            const int b = (c + 1) & 1;
            const int k0 = (c + 1) * 32;
#pragma unroll
            for (int i = 0; i < 4; i++) {
                cp16(sbA[b] + dstOff[i], srcA[i] + k0);
                cp16(sbB[b] + dstOff[i], srcB[i] + k0);
            }
            asm volatile("cp.async.commit_group;" ::: "memory");
            asm volatile("cp.async.wait_group 1;" ::: "memory");
        } else {
            asm volatile("cp.async.wait_group 0;" ::: "memory");
        }
        __syncthreads();

        const int b = c & 1;
        const uint32_t* As = reinterpret_cast<const uint32_t*>(bufA[b]);
        const uint32_t* Bs = reinterpret_cast<const uint32_t*>(bufB[b]);
#pragma unroll
        for (int k8 = 0; k8 < 4; k8++) {
            const int kc = k8 * 8 + t;
            uint32_t af[4][4];
#pragma unroll
            for (int mi = 0; mi < 4; mi++) {
                const uint32_t* ap = As + (wm * 64 + mi * 16 + g) * MG_STRIDE + kc;
                af[mi][0] = ap[0];
                af[mi][1] = ap[8 * MG_STRIDE];
                af[mi][2] = ap[4];
                af[mi][3] = ap[8 * MG_STRIDE + 4];
            }
            uint32_t bf[4][2];
#pragma unroll
            for (int ni = 0; ni < 4; ni++) {
                const uint32_t* bp = Bs + (wn * 32 + ni * 8 + g) * MG_STRIDE + kc;
                bf[ni][0] = bp[0];
                bf[ni][1] = bp[4];
            }
#pragma unroll
            for (int mi = 0; mi < 4; mi++)
#pragma unroll
                for (int ni = 0; ni < 4; ni++)
                    mma_tf32(acc[mi][ni], af[mi], bf[ni]);
        }
        __syncthreads();
    }

#pragma unroll
    for (int ni = 0; ni < 4; ni++) {
        const int col = n0 + wn * 32 + ni * 8 + 2 * t;
        float b0 = 0.f, b1 = 0.f;
        if (bias) { b0 = bias[col]; b1 = bias[col + 1]; }
#pragma unroll
        for (int mi = 0; mi < 4; mi++) {
            const int r0 = m0 + wm * 64 + mi * 16 + g;
            const int r1 = r0 + 8;
            if (r0 < Meff) {
                int ri = cmap ? sPerm[r0 - m0] : r0;
                float2 v = make_float2(acc[mi][ni][0] + b0, acc[mi][ni][1] + b1);
                *reinterpret_cast<float2*>(&C[(size_t)ri * ldc + col]) = v;
            }
            if (r1 < Meff) {
                int ri = cmap ? sPerm[r1 - m0] : r1;
                float2 v = make_float2(acc[mi][ni][2] + b0, acc[mi][ni][3] + b1);
                *reinterpret_cast<float2*>(&C[(size_t)ri * ldc + col]) = v;
            }
        }
    }
}

// ============ LSTM gates GEMM with FUSED cell epilogue ======================
// A = h_prev (permuted, tf32), B = g_whr2 (interleaved rows, K=512).
// Epilogue: lane pairs swap accumulators so each lane owns all 4 gates of one
// (row, j); applies rel/ent/bias gathers and the LSTM cell; writes c/h/pemb.
#define MGL_SMEM  (2048 + 4 * MG_BUF)
__global__ __launch_bounds__(256, 2) void mma_gemm_lstm(
    const float* __restrict__ A,
    float* __restrict__ h_next,
    const int* __restrict__ rel_idx, const int* __restrict__ ent_idx,
    const int* __restrict__ path_lens, const int* __restrict__ perm,
    const int* __restrict__ cntp, int tstep) {
    extern __shared__ char smem[];
    const int tid = threadIdx.x;
    const int wid = tid >> 5;
    const int lane = tid & 31;

    const int Meff = __ldg(cntp);
    const int m0 = blockIdx.y * 128;
    if (m0 >= Meff) return;
    const int n0 = blockIdx.x * 128;

    int* sRel = reinterpret_cast<int*>(smem);
    int* sEnt = reinterpret_cast<int*>(smem + 512);
    int* sLen = reinterpret_cast<int*>(smem + 1024);
    float* bufA[2] = { reinterpret_cast<float*>(smem + 2048),
                       reinterpret_cast<float*>(smem + 2048 + 2 * MG_BUF) };
    float* bufB[2] = { reinterpret_cast<float*>(smem + 2048 + MG_BUF),
                       reinterpret_cast<float*>(smem + 2048 + 3 * MG_BUF) };
    uint32_t sbA[2] = { smem_u32(bufA[0]), smem_u32(bufA[1]) };
    uint32_t sbB[2] = { smem_u32(bufB[0]), smem_u32(bufB[1]) };

    if (tid < 128) {
        int r = m0 + tid;
        if (r > Meff - 1) r = Meff - 1;
        int orig = perm[r];
        sRel[tid] = rel_idx[orig * LL + tstep];
        sEnt[tid] = ent_idx[orig * LL + tstep];
        sLen[tid] = path_lens[orig];
    }

    const int c4 = tid & 7;
    const float* srcA[4];
    const float* srcB[4];
    int dstOff[4];
#pragma unroll
    for (int i = 0; i < 4; i++) {
        int row = i * 32 + (tid >> 3);
        int r = m0 + row;
        if (r > Meff - 1) r = Meff - 1;
        srcA[i] = &A[(size_t)r * HH + c4 * 4];
        srcB[i] = &g_whr2[(size_t)(n0 + row) * HH + c4 * 4];
        dstOff[i] = row * (MG_STRIDE * 4) + c4 * 16;
    }

    const int nch = HH / 32;
    {
#pragma unroll
        for (int i = 0; i < 4; i++) {
            cp16(sbA[0] + dstOff[i], srcA[i]);
            cp16(sbB[0] + dstOff[i], srcB[i]);
        }
        asm volatile("cp.async.commit_group;" ::: "memory");
    }

    float acc[4][4][4];
#pragma unroll
    for (int mi = 0; mi < 4; mi++)
#pragma unroll
        for (int ni = 0; ni < 4; ni++)
#pragma unroll
            for (int q = 0; q < 4; q++) acc[mi][ni][q] = 0.f;

    const int lg = lane >> 2, lt = lane & 3;
    const int wm = wid >> 2, wn = wid & 3;

    for (int c = 0; c < nch; c++) {
        if (c + 1 < nch) {
            const int b = (c + 1) & 1;
            const int k0 = (c + 1) * 32;
#pragma unroll
            for (int i = 0; i < 4; i++) {
                cp16(sbA[b] + dstOff[i], srcA[i] + k0);
                cp16(sbB[b] + dstOff[i], srcB[i] + k0);
            }
            asm volatile("cp.async.commit_group;" ::: "memory");
            asm volatile("cp.async.wait_group 1;" ::: "memory");
        } else {
            asm volatile("cp.async.wait_group 0;" ::: "memory");
        }
        __syncthreads();

        const int b = c & 1;
        const uint32_t* As = reinterpret_cast<const uint32_t*>(bufA[b]);
        const uint32_t* Bs = reinterpret_cast<const uint32_t*>(bufB[b]);
#pragma unroll
        for (int k8 = 0; k8 < 4; k8++) {
            const int kc = k8 * 8 + lt;
            uint32_t af[4][4];
#pragma unroll
            for (int mi = 0; mi < 4; mi++) {
                const uint32_t* ap = As + (wm * 64 + mi * 16 + lg) * MG_STRIDE + kc;
                af[mi][0] = ap[0];
                af[mi][1] = ap[8 * MG_STRIDE];
                af[mi][2] = ap[4];
                af[mi][3] = ap[8 * MG_STRIDE + 4];
            }
            uint32_t bf[4][2];
#pragma unroll
            for (int ni = 0; ni < 4; ni++) {
                const uint32_t* bp = Bs + (wn * 32 + ni * 8 + lg) * MG_STRIDE + kc;
                bf[ni][0] = bp[0];
                bf[ni][1] = bp[4];
            }
#pragma unroll
            for (int mi = 0; mi < 4; mi++)
#pragma unroll
                for (int ni = 0; ni < 4; ni++)
                    mma_tf32(acc[mi][ni], af[mi], bf[ni]);
        }
        __syncthreads();
    }

    // ----- fused cell epilogue -----
    const bool odd = (lt & 1);
#pragma unroll
    for (int ni = 0; ni < 4; ni++) {
        const int jg = blockIdx.x * 32 + wn * 8 + ni * 2 + (lt >> 1);
        const float4 bc = ld4(&g_biasc[jg * 4]);
#pragma unroll
        for (int mi = 0; mi < 4; mi++) {
            float ex0 = __shfl_xor_sync(0xffffffffu, acc[mi][ni][0], 1);
            float ex1 = __shfl_xor_sync(0xffffffffu, acc[mi][ni][1], 1);
            float ex2 = __shfl_xor_sync(0xffffffffu, acc[mi][ni][2], 1);
            float ex3 = __shfl_xor_sync(0xffffffffu, acc[mi][ni][3], 1);
            float vi = odd ? ex2 : acc[mi][ni][0];
            float vf = odd ? ex3 : acc[mi][ni][1];
            float vg = odd ? acc[mi][ni][2] : ex0;
            float vo = odd ? acc[mi][ni][3] : ex1;
            const int row_l = wm * 64 + mi * 16 + lg + (odd ? 8 : 0);
            const int row = m0 + row_l;
            if (row < Meff) {
                const int ridx = sRel[row_l];
                const int eidx = sEnt[row_l];
                float4 rg = ld4(&g_rel_gate[(size_t)ridx * G4 + jg * 4]);
                float4 eg = ld4(&g_ent_gate[(size_t)eidx * G4 + jg * 4]);
                size_t off = (size_t)row * HH + jg;
                float cold = g_c[off];
                float gi = vi + rg.x + eg.x + bc.x;
                float gf = vf + rg.y + eg.y + bc.y;
                float gG = vg + rg.z + eg.z + bc.z;
                float gO = vo + rg.w + eg.w + bc.w;
                float cn = sigf(gf) * cold + sigf(gi) * tanhf(gG);
                float hn = tf32r(sigf(gO) * tanhf(cn));
                g_c[off] = cn;
                h_next[off] = hn;
                if (sLen[row_l] == tstep + 1) g_pemb[off] = hn;
            }
        }
    }
}

// ---------------- tf32 rounding copy ---------------------------------------
__global__ void round_tf32_kernel(const float* __restrict__ in, float* __restrict__ out, int n4) {
    int i = blockIdx.x * blockDim.x + threadIdx.x;
    if (i < n4) {
        float4 v = ld4(&in[i * 4]);
        v.x = tf32r(v.x); v.y = tf32r(v.y); v.z = tf32r(v.z); v.w = tf32r(v.w);
        *reinterpret_cast<float4*>(&out[i * 4]) = v;
    }
}

// ---------------- w_hh reorder+round: row n=j*4+gate <- w_hh[gate*512+j] ----
__global__ void reorder_whr_kernel(const float* __restrict__ w_hh) {
    int n = blockIdx.x;
    int src = (n & 3) * HH + (n >> 2);
    const float4* s = reinterpret_cast<const float4*>(&w_hh[(size_t)src * HH]);
    float4* d = reinterpret_cast<float4*>(&g_whr2[(size_t)n * HH]);
    int i = threadIdx.x;                 // 128 threads, HH/4 = 128
    float4 v = s[i];
    v.x = tf32r(v.x); v.y = tf32r(v.y); v.z = tf32r(v.z); v.w = tf32r(v.w);
    d[i] = v;
}

// ================= small fp32 GEMM (precompute, NN form) ====================
#define BM 128
#define BN 64
#define BK 16
#define TPB 256

template <bool ROUND, bool ROWMAP>
__global__ void gemm_nn_small(const float* __restrict__ A, const float* __restrict__ B,
                              float* __restrict__ C,
                              int M, int N, int Kd, int lda, int ldb, int ldc) {
    __shared__ float shA[BK][BM + 4];
    __shared__ float shB[BK][BN + 2];
    const int m0 = blockIdx.y * BM;
    const int n0 = blockIdx.x * BN;
    const int tid = threadIdx.x;
    const int jj = tid & 15;
    const int rg = tid >> 4;
    const int r0 = rg * 8;

    float acc[8][4];
#pragma unroll
    for (int i = 0; i < 8; i++)
#pragma unroll
        for (int q = 0; q < 4; q++) acc[i][q] = 0.0f;

    const int a_row = tid >> 2;
    const int a_k4  = (tid & 3) * 4;

    for (int k0 = 0; k0 < Kd; k0 += BK) {
#pragma unroll
        for (int hhalf = 0; hhalf < 2; hhalf++) {
            int r = a_row + hhalf * 64;
            int m = m0 + r;
            float4 v = make_float4(0.f, 0.f, 0.f, 0.f);
            if (m < M) v = ld4(&A[(size_t)m * lda + k0 + a_k4]);
            shA[a_k4 + 0][r] = v.x;
            shA[a_k4 + 1][r] = v.y;
            shA[a_k4 + 2][r] = v.z;
            shA[a_k4 + 3][r] = v.w;
        }
        {
            int kk2 = tid >> 4;
            int cc  = (tid & 15) * 4;
            float4 v = ld4(&B[(size_t)(k0 + kk2) * ldb + n0 + cc]);
            shB[kk2][cc + 0] = v.x;
            shB[kk2][cc + 1] = v.y;
            shB[kk2][cc + 2] = v.z;
            shB[kk2][cc + 3] = v.w;
        }
        __syncthreads();
#pragma unroll
        for (int k = 0; k < BK; k++) {
            float4 a01 = ld4(&shA[k][r0]);
            float4 a23 = ld4(&shA[k][r0 + 4]);
            float b0 = shB[k][jj], b1 = shB[k][jj + 16], b2 = shB[k][jj + 32], b3 = shB[k][jj + 48];
            float a[8] = {a01.x, a01.y, a01.z, a01.w, a23.x, a23.y, a23.z, a23.w};
#pragma unroll
            for (int i = 0; i < 8; i++) {
                acc[i][0] += a[i] * b0;
                acc[i][1] += a[i] * b1;
                acc[i][2] += a[i] * b2;
                acc[i][3] += a[i] * b3;
            }
        }
        __syncthreads();
    }
#pragma unroll
    for (int i = 0; i < 8; i++) {
        int m = m0 + r0 + i;
        if (m < M) {
            int mo = ROWMAP ? (((m & 511) << 2) | (m >> 9)) : m;   // gate*512+j -> j*4+gate
            float* crow = &C[(size_t)mo * ldc + n0];
            if (ROUND) {
                crow[jj]      = tf32r(acc[i][0]);
                crow[jj + 16] = tf32r(acc[i][1]);
                crow[jj + 32] = tf32r(acc[i][2]);
                crow[jj + 48] = tf32r(acc[i][3]);
            } else {
                crow[jj]      = acc[i][0];
                crow[jj + 16] = acc[i][1];
                crow[jj + 32] = acc[i][2];
                crow[jj + 48] = acc[i][3];
            }
        }
    }
}

// ---------------- combined gate bias (writes interleaved) ------------------
__global__ void biasc_kernel(const float* __restrict__ kg_proj_b, const float* __restrict__ w_ih,
                             const float* __restrict__ b_ih, const float* __restrict__ b_hh) {
    int g = blockIdx.x;                  // row of w_ih = gate*512+j
    float s = 0.f;
    const float* row = &w_ih[(size_t)g * (2 * HH)];
    for (int h = threadIdx.x; h < HH; h += 128) s += kg_proj_b[h] * (row[h] + row[HH + h]);
    __shared__ float red[128];
    red[threadIdx.x] = s;
    __syncthreads();
    for (int off = 64; off > 0; off >>= 1) {
        if (threadIdx.x < off) red[threadIdx.x] += red[threadIdx.x + off];
        __syncthreads();
    }
    if (threadIdx.x == 0) {
        int idx = ((g & 511) << 2) | (g >> 9);
        g_biasc[idx] = red[0] + b_ih[g] + b_hh[g];
    }
}

// ---------------- folded output bias ----------------------------------------
__global__ void biasfold_kernel(const float* __restrict__ ppw, const float* __restrict__ aob,
                                const float* __restrict__ ppb) {
    int i = blockIdx.x;
    float s = 0.f;
    const float* row = &ppw[(size_t)i * HH];
    for (int jx = threadIdx.x; jx < HH; jx += 128) s += row[jx] * aob[jx];
    __shared__ float red[128];
    red[threadIdx.x] = s;
    __syncthreads();
    for (int off = 64; off > 0; off >>= 1) {
        if (threadIdx.x < off) red[threadIdx.x] += red[threadIdx.x + off];
        __syncthreads();
    }
    if (threadIdx.x == 0) g_bc2[i] = red[0] + ppb[i];
}

// ---------------- counting sort by path length (descending) ----------------
__global__ void sort_init() {
    if (threadIdx.x < 4) g_bins[threadIdx.x] = 0;
}
__global__ void sort_count(const int* __restrict__ lens) {
    int n = blockIdx.x * blockDim.x + threadIdx.x;
    if (n < NPK) {
        int l = lens[n]; l = max(0, min(3, l));
        atomicAdd(&g_bins[3 - l], 1);
    }
}
__global__ void sort_prefix() {
    int c0 = g_bins[0], c1 = g_bins[1], c2 = g_bins[2];
    g_off[0] = 0; g_off[1] = c0; g_off[2] = c0 + c1; g_off[3] = c0 + c1 + c2;
    g_cnt[0] = c0; g_cnt[1] = c0 + c1; g_cnt[2] = c0 + c1 + c2;
}
__global__ void sort_scatter(const int* __restrict__ lens) {
    int n = blockIdx.x * blockDim.x + threadIdx.x;
    if (n < NPK) {
        int l = lens[n]; l = max(0, min(3, l));
        int pos = atomicAdd(&g_off[3 - l], 1);
        g_perm[pos] = n;
    }
}

// ---------------- LSTM step 0 (h=c=0), permuted layout, interleaved tables -
__global__ void step0_kernel(const int* __restrict__ rel_idx, const int* __restrict__ ent_idx,
                             const int* __restrict__ path_lens, const int* __restrict__ perm) {
    int n = blockIdx.x;
    int orig = perm[n];
    int ridx = rel_idx[orig * LL + 0];
    int eidx = ent_idx[orig * LL + 0];
    int len  = path_lens[orig];
    const float4* rg4 = reinterpret_cast<const float4*>(&g_rel_gate[(size_t)ridx * G4]);
    const float4* eg4 = reinterpret_cast<const float4*>(&g_ent_gate[(size_t)eidx * G4]);
    const float4* bc4 = reinterpret_cast<const float4*>(g_biasc);

#pragma unroll
    for (int it = 0; it < 4; it++) {
        int j = threadIdx.x + it * 128;
        float4 r = rg4[j], e = eg4[j], b = bc4[j];
        float gi = r.x + e.x + b.x;
        float gg = r.z + e.z + b.z;
        float go = r.w + e.w + b.w;
        float cn = sigf(gi) * tanhf(gg);
        float hn = tf32r(sigf(go) * tanhf(cn));
        size_t off = (size_t)n * HH + j;
        g_h0[off] = hn;
        g_c[off]  = cn;
        if (len == 1) g_pemb[off] = hn;
    }
}

// qkv rows for len==0 paths: pemb row = 0 -> qkv row = bias (orig layout)
__global__ void qkv_fill_kernel(const float* __restrict__ bias,
                                const int* __restrict__ perm, const int* __restrict__ cntp) {
    int m = blockIdx.x;
    if (m < __ldg(cntp)) return;
    int orig = perm[m];
    float4* row = reinterpret_cast<float4*>(&g_qkv[(size_t)orig * (3 * HH)]);
    const float4* b4 = reinterpret_cast<const float4*>(bias);
    for (int i = threadIdx.x; i < (3 * HH) / 4; i += blockDim.x) row[i] = b4[i];
}

// ---------------- per-pair attention; mean over K folded into column-sum ----
__global__ void attn_kernel() {
    int p = blockIdx.x;
    int tid = threadIdx.x;
    __shared__ float sq[KK][128], sk[KK][128], sv[KK][128];
    __shared__ float sc[KK][KK + 2];
    __shared__ float wcol[KK];

    for (int hd = 0; hd < 4; hd++) {
        for (int i = tid; i < KK * 128; i += 256) {
            int a = i >> 7, d = i & 127;
            size_t base = (size_t)(p * KK + a) * (3 * HH) + hd * 128 + d;
            sq[a][d] = g_qkv[base];
            sk[a][d] = g_qkv[base + HH];
            sv[a][d] = g_qkv[base + 2 * HH];
        }
        __syncthreads();
        if (tid < KK * KK) {
            int a = tid / KK, b = tid % KK;
            float s = 0.f;
#pragma unroll 8
            for (int d = 0; d < 128; d++) s += sq[a][d] * sk[b][d];
            sc[a][b] = s * 0.08838834764831845f;
        }
        __syncthreads();
        if (tid < KK) {
            int a = tid;
            float mx = -1e30f;
            for (int b = 0; b < KK; b++) mx = fmaxf(mx, sc[a][b]);
            float e[KK], sum = 0.f;
            for (int b = 0; b < KK; b++) { e[b] = expf(sc[a][b] - mx); sum += e[b]; }
            float inv = 1.f / sum;
            for (int b = 0; b < KK; b++) sc[a][b] = e[b] * inv;
        }
        __syncthreads();
        if (tid < KK) {
            int b = tid;
            float s = 0.f;
            for (int a = 0; a < KK; a++) s += sc[a][b];
            wcol[b] = s * 0.1f;
        }
        __syncthreads();
        if (tid < 128) {
            int d = tid;
            float s = 0.f;
#pragma unroll
            for (int b = 0; b < KK; b++) s += wcol[b] * sv[b][d];
            g_ctxmean[(size_t)p * HH + hd * 128 + d] = tf32r(s);  // rounded: GEMM input
        }
        __syncthreads();
    }
}

// ---------------- launch --------------------------------------------------
extern "C" void kernel_launch(void* const* d_in, const int* in_sizes, int n_in,
                              void* d_out, int out_size) {
    const int*   rel_idx     = (const int*)d_in[0];
    const int*   ent_idx     = (const int*)d_in[1];
    const int*   path_lens   = (const int*)d_in[2];
    const float* rel_table   = (const float*)d_in[3];
    const float* ent_table   = (const float*)d_in[4];
    const float* kg_proj_w   = (const float*)d_in[5];
    const float* kg_proj_b   = (const float*)d_in[6];
    const float* w_ih        = (const float*)d_in[7];
    const float* w_hh        = (const float*)d_in[8];
    const float* b_ih        = (const float*)d_in[9];
    const float* b_hh        = (const float*)d_in[10];
    const float* attn_in_w   = (const float*)d_in[11];
    const float* attn_in_b   = (const float*)d_in[12];
    const float* attn_out_w  = (const float*)d_in[13];
    const float* attn_out_b  = (const float*)d_in[14];
    const float* path_proj_w = (const float*)d_in[15];
    const float* path_proj_b = (const float*)d_in[16];
    float* out = (float*)d_out;

    float *pW1, *pW2, *pRel, *pEnt, *pH0, *pH1, *pPemb, *pQkv, *pCtx, *pWc, *pBc2;
    float *pAiw, *pEntr, *pRelr;
    int *pPerm, *pCnt;
    cudaGetSymbolAddress((void**)&pW1, g_W1);
    cudaGetSymbolAddress((void**)&pW2, g_W2);
    cudaGetSymbolAddress((void**)&pRel, g_rel_gate);
    cudaGetSymbolAddress((void**)&pEnt, g_ent_gate);
    cudaGetSymbolAddress((void**)&pH0, g_h0);
    cudaGetSymbolAddress((void**)&pH1, g_h1);
    cudaGetSymbolAddress((void**)&pPemb, g_pemb);
    cudaGetSymbolAddress((void**)&pQkv, g_qkv);
    cudaGetSymbolAddress((void**)&pCtx, g_ctxmean);
    cudaGetSymbolAddress((void**)&pWc, g_Wc);
    cudaGetSymbolAddress((void**)&pBc2, g_bc2);
    cudaGetSymbolAddress((void**)&pAiw, g_aiw);
    cudaGetSymbolAddress((void**)&pEntr, g_entr);
    cudaGetSymbolAddress((void**)&pRelr, g_relr);
    cudaGetSymbolAddress((void**)&pPerm, g_perm);
    cudaGetSymbolAddress((void**)&pCnt, g_cnt);

    cudaFuncSetAttribute(mma_gemm, cudaFuncAttributeMaxDynamicSharedMemorySize, MG_SMEM);
    cudaFuncSetAttribute(mma_gemm_lstm, cudaFuncAttributeMaxDynamicSharedMemorySize, MGL_SMEM);

    // --- precompute ---
    gemm_nn_small<true, true><<<dim3(EE / BN, G4 / BM), TPB>>>(w_ih,      kg_proj_w, pW1,
                                                               G4, EE, HH, 2 * HH, EE, EE);
    gemm_nn_small<true, true><<<dim3(EE / BN, G4 / BM), TPB>>>(w_ih + HH, kg_proj_w, pW2,
                                                               G4, EE, HH, 2 * HH, EE, EE);
    round_tf32_kernel<<<(NENT * EE / 4 + 255) / 256, 256>>>(ent_table, pEntr, NENT * EE / 4);
    round_tf32_kernel<<<(NREL * EE / 4 + 255) / 256, 256>>>(rel_table, pRelr, NREL * EE / 4);
    round_tf32_kernel<<<(3 * HH * HH / 4 + 255) / 256, 256>>>(attn_in_w, pAiw, 3 * HH * HH / 4);
    // per-entity gate tables (interleaved cols via interleaved W rows)
    mma_gemm<<<dim3(G4 / 128, (NENT + 127) / 128), 256, MG_SMEM>>>(
        pEntr, EE, pW2, nullptr, pEnt, G4, NENT, EE, nullptr, nullptr);
    mma_gemm<<<dim3(G4 / 128, (NREL + 127) / 128), 256, MG_SMEM>>>(
        pRelr, EE, pW1, nullptr, pRel, G4, NREL, EE, nullptr, nullptr);

    // --- counting sort by path length (descending) ---
    sort_init<<<1, 32>>>();
    sort_count<<<(NPK + 255) / 256, 256>>>(path_lens);
    sort_prefix<<<1, 1>>>();
    sort_scatter<<<(NPK + 255) / 256, 256>>>(path_lens);

    reorder_whr_kernel<<<G4, 128>>>(w_hh);
    biasc_kernel<<<G4, 128>>>(kg_proj_b, w_ih, b_ih, b_hh);

    // folded output projection: Wc = ppw@aow (rounded), bc2 = ppw@aob + ppb
    gemm_nn_small<true, false><<<dim3(HH / BN, HH / BM), TPB>>>(path_proj_w, attn_out_w, pWc,
                                                                HH, HH, HH, HH, HH, HH);
    biasfold_kernel<<<HH, 128>>>(path_proj_w, attn_out_b, path_proj_b);

    // --- LSTM: step0 gather; steps 1,2 fused GEMM+cell on compacted prefix ---
    step0_kernel<<<NPK, 128>>>(rel_idx, ent_idx, path_lens, pPerm);
    mma_gemm_lstm<<<dim3(G4 / 128, NPK / 128), 256, MGL_SMEM>>>(
        pH0, pH1, rel_idx, ent_idx, path_lens, pPerm, pCnt + 1, 1);
    mma_gemm_lstm<<<dim3(G4 / 128, NPK / 128), 256, MGL_SMEM>>>(
        pH1, pH0, rel_idx, ent_idx, path_lens, pPerm, pCnt + 0, 2);

    // --- QKV projection (compacted pemb rows; scatter to original layout) ---
    mma_gemm<<<dim3(3 * HH / 128, NPK / 128), 256, MG_SMEM>>>(
        pPemb, HH, pAiw, attn_in_b, pQkv, 3 * HH, NPK, HH, pCnt + 2, pPerm);
    qkv_fill_kernel<<<NPK, 128>>>(attn_in_b, pPerm, pCnt + 2);

    // --- attention with folded mean -> ctxmean ---
    attn_kernel<<<PP, 256>>>();

    // --- single folded output GEMM: out = ctxmean @ Wc^T + bc2 ---
    mma_gemm<<<dim3(HH / 128, PP / 128), 256, MG_SMEM>>>(
        pCtx, HH, pWc, pBc2, out, HH, PP, HH, nullptr, nullptr);
}

// round 17
// speedup vs baseline: 1.1853x; 1.0741x over previous
#include <cuda_runtime.h>
#include <cuda_bf16.h>
#include <math.h>
#include <stdint.h>

// Problem constants
#define PP    2048
#define KK    10
#define LL    3
#define EE    256
#define HH    512
#define G4    2048      // 4*H
#define NPK   20480     // P*K
#define NENT  10000
#define NREL  200

// ---------------- scratch (static device globals; no allocs) ----------------
// NOTE: gate-dimension layout is INTERLEAVED everywhere: index = j*4 + gate
__device__ float g_W12[2 * G4 * EE];     // [0]=W1 rows (interleaved), [G4..)=W2
__device__ float g_biasc[G4];            // interleaved combined gate bias
__device__ float g_Wc[HH * HH];          // tf32-rounded (path_proj_w @ attn_out_w)
__device__ float g_bc2[HH];              // ppw@aob + ppb
__device__ float g_rel_gate[NREL * G4];  // interleaved cols
__device__ float g_ent_gate[NENT * G4];  // interleaved cols
__device__ float g_h0[NPK * HH];         // permuted layout, tf32-rounded
__device__ float g_h1[NPK * HH];         // permuted layout, tf32-rounded
__device__ float g_c[NPK * HH];          // permuted layout, exact fp32
__device__ float g_pemb[NPK * HH];       // PERMUTED layout, tf32-rounded
__device__ float g_qkv[NPK * 3 * HH];    // ORIGINAL layout: q | k | v
__device__ float g_ctxmean[PP * HH];     // tf32-rounded
// tf32-rounded operand copies
__device__ float g_whr2[G4 * HH];        // w_hh rows interleaved + rounded
__device__ float g_wihr[G4 * 2 * HH];    // w_ih rounded ([4096,512] view)
__device__ float g_kgwT[EE * HH];        // kg_proj_w transposed + rounded [256,512]
__device__ float g_aiw[3 * HH * HH];     // attn_in_w rounded
__device__ float g_entr[NENT * EE];
__device__ float g_relr[NREL * EE];
__device__ int   g_wmap[2 * G4];         // W12 fold row-scatter map

// length-sort state
__device__ int g_bins[4];
__device__ int g_off[4];
__device__ int g_cnt[3];                 // [0]=#len3, [1]=#len>=2, [2]=#len>=1
__device__ int g_perm[NPK];              // permuted -> original

__device__ __forceinline__ float sigf(float x) { return 1.0f / (1.0f + expf(-x)); }
__device__ __forceinline__ float4 ld4(const float* p) { return *reinterpret_cast<const float4*>(p); }
__device__ __forceinline__ float tf32r(float x) {
    uint32_t r;
    asm("cvt.rna.tf32.f32 %0, %1;" : "=r"(r) : "f"(x));
    return __uint_as_float(r);
}
__device__ __forceinline__ uint32_t smem_u32(const void* p) {
    uint32_t a;
    asm("{ .reg .u64 tmp; cvta.to.shared.u64 tmp, %1; cvt.u32.u64 %0, tmp; }" : "=r"(a) : "l"(p));
    return a;
}
__device__ __forceinline__ void cp16(uint32_t dst, const void* src) {
    asm volatile("cp.async.cg.shared.global [%0], [%1], 16;" :: "r"(dst), "l"(src) : "memory");
}
__device__ __forceinline__ void mma_tf32(float* c, const uint32_t* a, const uint32_t* b) {
    asm volatile(
        "mma.sync.aligned.m16n8k8.row.col.f32.tf32.tf32.f32 "
        "{%0,%1,%2,%3}, {%4,%5,%6,%7}, {%8,%9}, {%0,%1,%2,%3};"
        : "+f"(c[0]), "+f"(c[1]), "+f"(c[2]), "+f"(c[3])
        : "r"(a[0]), "r"(a[1]), "r"(a[2]), "r"(a[3]), "r"(b[0]), "r"(b[1]));
}

#define MG_STRIDE 36
#define MG_BUF    18432

// ==================== generic mma.sync tf32 GEMM ============================
// C[M,N] = A[M,K] @ B[N,K]^T (+bias). ldb == Kd. cmap = C-row scatter ONLY.
#define MG_SMEM   (1024 + 4 * MG_BUF)
__global__ __launch_bounds__(256, 2) void mma_gemm(
    const float* __restrict__ A, int lda,
    const float* __restrict__ B,
    const float* __restrict__ bias,
    float* __restrict__ C, int ldc,
    int M, int Kd,
    const int* __restrict__ cntp,
    const int* __restrict__ cmap) {
    extern __shared__ char smem[];
    const int tid = threadIdx.x;
    const int wid = tid >> 5;
    const int lane = tid & 31;

    int Meff = M;
    if (cntp) { int cv = __ldg(cntp); Meff = (cv < M) ? cv : M; }
    const int m0 = blockIdx.y * 128;
    if (m0 >= Meff) return;
    const int n0 = blockIdx.x * 128;

    int* sPerm = reinterpret_cast<int*>(smem);
    float* bufA[2] = { reinterpret_cast<float*>(smem + 1024),
                       reinterpret_cast<float*>(smem + 1024 + 2 * MG_BUF) };
    float* bufB[2] = { reinterpret_cast<float*>(smem + 1024 + MG_BUF),
                       reinterpret_cast<float*>(smem + 1024 + 3 * MG_BUF) };
    uint32_t sbA[2] = { smem_u32(bufA[0]), smem_u32(bufA[1]) };
    uint32_t sbB[2] = { smem_u32(bufB[0]), smem_u32(bufB[1]) };

    if (cmap && tid < 128) sPerm[tid] = cmap[m0 + tid];
    __syncthreads();

    const int c4 = tid & 7;
    const float* srcA[4];
    const float* srcB[4];
    int dstOff[4];
#pragma unroll
    for (int i = 0; i < 4; i++) {
        int row = i * 32 + (tid >> 3);
        int r = m0 + row;
        if (r > Meff - 1) r = Meff - 1;
        srcA[i] = &A[(size_t)r * lda + c4 * 4];
        srcB[i] = &B[(size_t)(n0 + row) * Kd + c4 * 4];
        dstOff[i] = row * (MG_STRIDE * 4) + c4 * 16;
    }

    const int nch = Kd / 32;
    {
#pragma unroll
        for (int i = 0; i < 4; i++) {
            cp16(sbA[0] + dstOff[i], srcA[i]);
            cp16(sbB[0] + dstOff[i], srcB[i]);
        }
        asm volatile("cp.async.commit_group;" ::: "memory");
    }

    float acc[4][4][4];
#pragma unroll
    for (int mi = 0; mi < 4; mi++)
#pragma unroll
        for (int ni = 0; ni < 4; ni++)
#pragma unroll
            for (int q = 0; q < 4; q++) acc[mi][ni][q] = 0.f;

    const int g = lane >> 2, t = lane & 3;
    const int wm = wid >> 2, wn = wid & 3;

    for (int c = 0; c < nch; c++) {
        if (c + 1 < nch) {
            const int b = (c + 1) & 1;
            const int k0 = (c + 1) * 32;
#pragma unroll
            for (int i = 0; i < 4; i++) {
                cp16(sbA[b] + dstOff[i], srcA[i] + k0);
                cp16(sbB[b] + dstOff[i], srcB[i] + k0);
            }
            asm volatile("cp.async.commit_group;" ::: "memory");
            asm volatile("cp.async.wait_group 1;" ::: "memory");
        } else {
            asm volatile("cp.async.wait_group 0;" ::: "memory");
        }
        __syncthreads();

        const int b = c & 1;
        const uint32_t* As = reinterpret_cast<const uint32_t*>(bufA[b]);
        const uint32_t* Bs = reinterpret_cast<const uint32_t*>(bufB[b]);
#pragma unroll
        for (int k8 = 0; k8 < 4; k8++) {
            const int kc = k8 * 8 + t;
            uint32_t af[4][4];
#pragma unroll
            for (int mi = 0; mi < 4; mi++) {
                const uint32_t* ap = As + (wm * 64 + mi * 16 + g) * MG_STRIDE + kc;
                af[mi][0] = ap[0];
                af[mi][1] = ap[8 * MG_STRIDE];
                af[mi][2] = ap[4];
                af[mi][3] = ap[8 * MG_STRIDE + 4];
            }
            uint32_t bf[4][2];
#pragma unroll
            for (int ni = 0; ni < 4; ni++) {
                const uint32_t* bp = Bs + (wn * 32 + ni * 8 + g) * MG_STRIDE + kc;
                bf[ni][0] = bp[0];
                bf[ni][1] = bp[4];
            }
#pragma unroll
            for (int mi = 0; mi < 4; mi++)
#pragma unroll
                for (int ni = 0; ni < 4; ni++)
                    mma_tf32(acc[mi][ni], af[mi], bf[ni]);
        }
        __syncthreads();
    }

#pragma unroll
    for (int ni = 0; ni < 4; ni++) {
        const int col = n0 + wn * 32 + ni * 8 + 2 * t;
        float b0 = 0.f, b1 = 0.f;
        if (bias) { b0 = bias[col]; b1 = bias[col + 1]; }
#pragma unroll
        for (int mi = 0; mi < 4; mi++) {
            const int r0 = m0 + wm * 64 + mi * 16 + g;
            const int r1 = r0 + 8;
            if (r0 < Meff) {
                int ri = cmap ? sPerm[r0 - m0] : r0;
                float2 v = make_float2(acc[mi][ni][0] + b0, acc[mi][ni][1] + b1);
                *reinterpret_cast<float2*>(&C[(size_t)ri * ldc + col]) = v;
            }
            if (r1 < Meff) {
                int ri = cmap ? sPerm[r1 - m0] : r1;
                float2 v = make_float2(acc[mi][ni][2] + b0, acc[mi][ni][3] + b1);
                *reinterpret_cast<float2*>(&C[(size_t)ri * ldc + col]) = v;
            }
        }
    }
}

// ============ LSTM gates GEMM with FUSED cell epilogue ======================
#define MGL_SMEM  (2048 + 4 * MG_BUF)
__global__ __launch_bounds__(256, 2) void mma_gemm_lstm(
    const float* __restrict__ A,
    float* __restrict__ h_next,
    const int* __restrict__ rel_idx, const int* __restrict__ ent_idx,
    const int* __restrict__ path_lens, const int* __restrict__ perm,
    const int* __restrict__ cntp, int tstep) {
    extern __shared__ char smem[];
    const int tid = threadIdx.x;
    const int wid = tid >> 5;
    const int lane = tid & 31;

    const int Meff = __ldg(cntp);
    const int m0 = blockIdx.y * 128;
    if (m0 >= Meff) return;
    const int n0 = blockIdx.x * 128;

    int* sRel = reinterpret_cast<int*>(smem);
    int* sEnt = reinterpret_cast<int*>(smem + 512);
    int* sLen = reinterpret_cast<int*>(smem + 1024);
    float* bufA[2] = { reinterpret_cast<float*>(smem + 2048),
                       reinterpret_cast<float*>(smem + 2048 + 2 * MG_BUF) };
    float* bufB[2] = { reinterpret_cast<float*>(smem + 2048 + MG_BUF),
                       reinterpret_cast<float*>(smem + 2048 + 3 * MG_BUF) };
    uint32_t sbA[2] = { smem_u32(bufA[0]), smem_u32(bufA[1]) };
    uint32_t sbB[2] = { smem_u32(bufB[0]), smem_u32(bufB[1]) };

    if (tid < 128) {
        int r = m0 + tid;
        if (r > Meff - 1) r = Meff - 1;
        int orig = perm[r];
        sRel[tid] = rel_idx[orig * LL + tstep];
        sEnt[tid] = ent_idx[orig * LL + tstep];
        sLen[tid] = path_lens[orig];
    }

    const int c4 = tid & 7;
    const float* srcA[4];
    const float* srcB[4];
    int dstOff[4];
#pragma unroll
    for (int i = 0; i < 4; i++) {
        int row = i * 32 + (tid >> 3);
        int r = m0 + row;
        if (r > Meff - 1) r = Meff - 1;
        srcA[i] = &A[(size_t)r * HH + c4 * 4];
        srcB[i] = &g_whr2[(size_t)(n0 + row) * HH + c4 * 4];
        dstOff[i] = row * (MG_STRIDE * 4) + c4 * 16;
    }

    const int nch = HH / 32;
    {
#pragma unroll
        for (int i = 0; i < 4; i++) {
            cp16(sbA[0] + dstOff[i], srcA[i]);
            cp16(sbB[0] + dstOff[i], srcB[i]);
        }
        asm volatile("cp.async.commit_group;" ::: "memory");
    }

    float acc[4][4][4];
#pragma unroll
    for (int mi = 0; mi < 4; mi++)
#pragma unroll
        for (int ni = 0; ni < 4; ni++)
#pragma unroll
            for (int q = 0; q < 4; q++) acc[mi][ni][q] = 0.f;

    const int lg = lane >> 2, lt = lane & 3;
    const int wm = wid >> 2, wn = wid & 3;

    for (int c = 0; c < nch; c++) {
        if (c + 1 < nch) {
            const int b = (c + 1) & 1;
            const int k0 = (c + 1) * 32;
#pragma unroll
            for (int i = 0; i < 4; i++) {
                cp16(sbA[b] + dstOff[i], srcA[i] + k0);
                cp16(sbB[b] + dstOff[i], srcB[i] + k0);
            }
            asm volatile("cp.async.commit_group;" ::: "memory");
            asm volatile("cp.async.wait_group 1;" ::: "memory");
        } else {
            asm volatile("cp.async.wait_group 0;" ::: "memory");
        }
        __syncthreads();

        const int b = c & 1;
        const uint32_t* As = reinterpret_cast<const uint32_t*>(bufA[b]);
        const uint32_t* Bs = reinterpret_cast<const uint32_t*>(bufB[b]);
#pragma unroll
        for (int k8 = 0; k8 < 4; k8++) {
            const int kc = k8 * 8 + lt;
            uint32_t af[4][4];
#pragma unroll
            for (int mi = 0; mi < 4; mi++) {
                const uint32_t* ap = As + (wm * 64 + mi * 16 + lg) * MG_STRIDE + kc;
                af[mi][0] = ap[0];
                af[mi][1] = ap[8 * MG_STRIDE];
                af[mi][2] = ap[4];
                af[mi][3] = ap[8 * MG_STRIDE + 4];
            }
            uint32_t bf[4][2];
#pragma unroll
            for (int ni = 0; ni < 4; ni++) {
                const uint32_t* bp = Bs + (wn * 32 + ni * 8 + lg) * MG_STRIDE + kc;
                bf[ni][0] = bp[0];
                bf[ni][1] = bp[4];
            }
#pragma unroll
            for (int mi = 0; mi < 4; mi++)
#pragma unroll
                for (int ni = 0; ni < 4; ni++)
                    mma_tf32(acc[mi][ni], af[mi], bf[ni]);
        }
        __syncthreads();
    }

    // ----- fused cell epilogue -----
    const bool odd = (lt & 1);
#pragma unroll
    for (int ni = 0; ni < 4; ni++) {
        const int jg = blockIdx.x * 32 + wn * 8 + ni * 2 + (lt >> 1);
        const float4 bc = ld4(&g_biasc[jg * 4]);
#pragma unroll
        for (int mi = 0; mi < 4; mi++) {
            float ex0 = __shfl_xor_sync(0xffffffffu, acc[mi][ni][0], 1);
            float ex1 = __shfl_xor_sync(0xffffffffu, acc[mi][ni][1], 1);
            float ex2 = __shfl_xor_sync(0xffffffffu, acc[mi][ni][2], 1);
            float ex3 = __shfl_xor_sync(0xffffffffu, acc[mi][ni][3], 1);
            float vi = odd ? ex2 : acc[mi][ni][0];
            float vf = odd ? ex3 : acc[mi][ni][1];
            float vg = odd ? acc[mi][ni][2] : ex0;
            float vo = odd ? acc[mi][ni][3] : ex1;
            const int row_l = wm * 64 + mi * 16 + lg + (odd ? 8 : 0);
            const int row = m0 + row_l;
            if (row < Meff) {
                const int ridx = sRel[row_l];
                const int eidx = sEnt[row_l];
                float4 rg = ld4(&g_rel_gate[(size_t)ridx * G4 + jg * 4]);
                float4 eg = ld4(&g_ent_gate[(size_t)eidx * G4 + jg * 4]);
                size_t off = (size_t)row * HH + jg;
                float cold = g_c[off];
                float gi = vi + rg.x + eg.x + bc.x;
                float gf = vf + rg.y + eg.y + bc.y;
                float gG = vg + rg.z + eg.z + bc.z;
                float gO = vo + rg.w + eg.w + bc.w;
                float cn = sigf(gf) * cold + sigf(gi) * tanhf(gG);
                float hn = tf32r(sigf(gO) * tanhf(cn));
                g_c[off] = cn;
                h_next[off] = hn;
                if (sLen[row_l] == tstep + 1) g_pemb[off] = hn;
            }
        }
    }
}

// ---------------- fused 4-segment tf32 rounding copy ------------------------
__global__ void round4_kernel(const float* __restrict__ s0, float* __restrict__ d0, int n0,
                              const float* __restrict__ s1, float* __restrict__ d1, int n1,
                              const float* __restrict__ s2, float* __restrict__ d2, int n2,
                              const float* __restrict__ s3, float* __restrict__ d3, int n3) {
    int j = blockIdx.x * blockDim.x + threadIdx.x;
    const float* s;
    float* d;
    if (j < n0) { s = s0; d = d0; }
    else {
        j -= n0;
        if (j < n1) { s = s1; d = d1; }
        else {
            j -= n1;
            if (j < n2) { s = s2; d = d2; }
            else {
                j -= n2;
                if (j >= n3) return;
                s = s3; d = d3;
            }
        }
    }
    float4 v = ld4(&s[(size_t)j * 4]);
    v.x = tf32r(v.x); v.y = tf32r(v.y); v.z = tf32r(v.z); v.w = tf32r(v.w);
    *reinterpret_cast<float4*>(&d[(size_t)j * 4]) = v;
}

// ---------------- kg_proj_w transpose + round: [512,256] -> [256,512] ------
__global__ void kgwT_kernel(const float* __restrict__ kgw) {
    int idx = blockIdx.x * 256 + threadIdx.x;   // 0 .. EE*HH
    if (idx < EE * HH) {
        int e = idx >> 9, h = idx & 511;
        g_kgwT[idx] = tf32r(kgw[h * EE + e]);
    }
}

// ---------------- W12 fold row map: m=2g+half -> half*G4 + (j*4+gate) -------
__global__ void wmap_kernel() {
    int m = blockIdx.x * 256 + threadIdx.x;
    if (m < 2 * G4) {
        int g = m >> 1;
        g_wmap[m] = (m & 1) * G4 + (((g & 511) << 2) | (g >> 9));
    }
}

// ---------------- w_hh reorder+round: row n=j*4+gate <- w_hh[gate*512+j] ----
__global__ void reorder_whr_kernel(const float* __restrict__ w_hh) {
    int n = blockIdx.x;
    int src = (n & 3) * HH + (n >> 2);
    const float4* s = reinterpret_cast<const float4*>(&w_hh[(size_t)src * HH]);
    float4* d = reinterpret_cast<float4*>(&g_whr2[(size_t)n * HH]);
    int i = threadIdx.x;
    float4 v = s[i];
    v.x = tf32r(v.x); v.y = tf32r(v.y); v.z = tf32r(v.z); v.w = tf32r(v.w);
    d[i] = v;
}

// ================= small fp32 GEMM (precompute, NN form) ====================
#define BM 128
#define BN 64
#define BK 16
#define TPB 256

__global__ void gemm_nn_small(const float* __restrict__ A, const float* __restrict__ B,
                              float* __restrict__ C,
                              int M, int N, int Kd, int lda, int ldb, int ldc) {
    __shared__ float shA[BK][BM + 4];
    __shared__ float shB[BK][BN + 2];
    const int m0 = blockIdx.y * BM;
    const int n0 = blockIdx.x * BN;
    const int tid = threadIdx.x;
    const int jj = tid & 15;
    const int rg = tid >> 4;
    const int r0 = rg * 8;

    float acc[8][4];
#pragma unroll
    for (int i = 0; i < 8; i++)
#pragma unroll
        for (int q = 0; q < 4; q++) acc[i][q] = 0.0f;

    const int a_row = tid >> 2;
    const int a_k4  = (tid & 3) * 4;

    for (int k0 = 0; k0 < Kd; k0 += BK) {
#pragma unroll
        for (int hhalf = 0; hhalf < 2; hhalf++) {
            int r = a_row + hhalf * 64;
            int m = m0 + r;
            float4 v = make_float4(0.f, 0.f, 0.f, 0.f);
            if (m < M) v = ld4(&A[(size_t)m * lda + k0 + a_k4]);
            shA[a_k4 + 0][r] = v.x;
            shA[a_k4 + 1][r] = v.y;
            shA[a_k4 + 2][r] = v.z;
            shA[a_k4 + 3][r] = v.w;
        }
        {
            int kk2 = tid >> 4;
            int cc  = (tid & 15) * 4;
            float4 v = ld4(&B[(size_t)(k0 + kk2) * ldb + n0 + cc]);
            shB[kk2][cc + 0] = v.x;
            shB[kk2][cc + 1] = v.y;
            shB[kk2][cc + 2] = v.z;
            shB[kk2][cc + 3] = v.w;
        }
        __syncthreads();
#pragma unroll
        for (int k = 0; k < BK; k++) {
            float4 a01 = ld4(&shA[k][r0]);
            float4 a23 = ld4(&shA[k][r0 + 4]);
            float b0 = shB[k][jj], b1 = shB[k][jj + 16], b2 = shB[k][jj + 32], b3 = shB[k][jj + 48];
            float a[8] = {a01.x, a01.y, a01.z, a01.w, a23.x, a23.y, a23.z, a23.w};
#pragma unroll
            for (int i = 0; i < 8; i++) {
                acc[i][0] += a[i] * b0;
                acc[i][1] += a[i] * b1;
                acc[i][2] += a[i] * b2;
                acc[i][3] += a[i] * b3;
            }
        }
        __syncthreads();
    }
#pragma unroll
    for (int i = 0; i < 8; i++) {
        int m = m0 + r0 + i;
        if (m < M) {
            float* crow = &C[(size_t)m * ldc + n0];
            crow[jj]      = tf32r(acc[i][0]);
            crow[jj + 16] = tf32r(acc[i][1]);
            crow[jj + 32] = tf32r(acc[i][2]);
            crow[jj + 48] = tf32r(acc[i][3]);
        }
    }
}

// ---------------- combined gate bias (writes interleaved) ------------------
__global__ void biasc_kernel(const float* __restrict__ kg_proj_b, const float* __restrict__ w_ih,
                             const float* __restrict__ b_ih, const float* __restrict__ b_hh) {
    int g = blockIdx.x;                  // row of w_ih = gate*512+j
    float s = 0.f;
    const float* row = &w_ih[(size_t)g * (2 * HH)];
    for (int h = threadIdx.x; h < HH; h += 128) s += kg_proj_b[h] * (row[h] + row[HH + h]);
    __shared__ float red[128];
    red[threadIdx.x] = s;
    __syncthreads();
    for (int off = 64; off > 0; off >>= 1) {
        if (threadIdx.x < off) red[threadIdx.x] += red[threadIdx.x + off];
        __syncthreads();
    }
    if (threadIdx.x == 0) {
        int idx = ((g & 511) << 2) | (g >> 9);
        g_biasc[idx] = red[0] + b_ih[g] + b_hh[g];
    }
}

// ---------------- folded output bias ----------------------------------------
__global__ void biasfold_kernel(const float* __restrict__ ppw, const float* __restrict__ aob,
                                const float* __restrict__ ppb) {
    int i = blockIdx.x;
    float s = 0.f;
    const float* row = &ppw[(size_t)i * HH];
    for (int jx = threadIdx.x; jx < HH; jx += 128) s += row[jx] * aob[jx];
    __shared__ float red[128];
    red[threadIdx.x] = s;
    __syncthreads();
    for (int off = 64; off > 0; off >>= 1) {
        if (threadIdx.x < off) red[threadIdx.x] += red[threadIdx.x + off];
        __syncthreads();
    }
    if (threadIdx.x == 0) g_bc2[i] = red[0] + ppb[i];
}

// ---------------- counting sort by path length (descending) ----------------
__global__ void sort_init() {
    if (threadIdx.x < 4) g_bins[threadIdx.x] = 0;
}
__global__ void sort_count(const int* __restrict__ lens) {
    int n = blockIdx.x * blockDim.x + threadIdx.x;
    if (n < NPK) {
        int l = lens[n]; l = max(0, min(3, l));
        atomicAdd(&g_bins[3 - l], 1);
    }
}
__global__ void sort_prefix() {
    int c0 = g_bins[0], c1 = g_bins[1], c2 = g_bins[2];
    g_off[0] = 0; g_off[1] = c0; g_off[2] = c0 + c1; g_off[3] = c0 + c1 + c2;
    g_cnt[0] = c0; g_cnt[1] = c0 + c1; g_cnt[2] = c0 + c1 + c2;
}
__global__ void sort_scatter(const int* __restrict__ lens) {
    int n = blockIdx.x * blockDim.x + threadIdx.x;
    if (n < NPK) {
        int l = lens[n]; l = max(0, min(3, l));
        int pos = atomicAdd(&g_off[3 - l], 1);
        g_perm[pos] = n;
    }
}

// ---------------- LSTM step 0 (h=c=0), permuted layout, interleaved tables -
__global__ void step0_kernel(const int* __restrict__ rel_idx, const int* __restrict__ ent_idx,
                             const int* __restrict__ path_lens, const int* __restrict__ perm) {
    int n = blockIdx.x;
    int orig = perm[n];
    int ridx = rel_idx[orig * LL + 0];
    int eidx = ent_idx[orig * LL + 0];
    int len  = path_lens[orig];
    const float4* rg4 = reinterpret_cast<const float4*>(&g_rel_gate[(size_t)ridx * G4]);
    const float4* eg4 = reinterpret_cast<const float4*>(&g_ent_gate[(size_t)eidx * G4]);
    const float4* bc4 = reinterpret_cast<const float4*>(g_biasc);

#pragma unroll
    for (int it = 0; it < 4; it++) {
        int j = threadIdx.x + it * 128;
        float4 r = rg4[j], e = eg4[j], b = bc4[j];
        float gi = r.x + e.x + b.x;
        float gg = r.z + e.z + b.z;
        float go = r.w + e.w + b.w;
        float cn = sigf(gi) * tanhf(gg);
        float hn = tf32r(sigf(go) * tanhf(cn));
        size_t off = (size_t)n * HH + j;
        g_h0[off] = hn;
        g_c[off]  = cn;
        if (len == 1) g_pemb[off] = hn;
    }
}

// qkv rows for len==0 paths: pemb row = 0 -> qkv row = bias (orig layout)
__global__ void qkv_fill_kernel(const float* __restrict__ bias,
                                const int* __restrict__ perm, const int* __restrict__ cntp) {
    int m = blockIdx.x;
    if (m < __ldg(cntp)) return;
    int orig = perm[m];
    float4* row = reinterpret_cast<float4*>(&g_qkv[(size_t)orig * (3 * HH)]);
    const float4* b4 = reinterpret_cast<const float4*>(bias);
    for (int i = threadIdx.x; i < (3 * HH) / 4; i += blockDim.x) row[i] = b4[i];
}

// ---------------- per-pair attention; mean over K folded into column-sum ----
__global__ void attn_kernel() {
    int p = blockIdx.x;
    int tid = threadIdx.x;
    __shared__ float sq[KK][128], sk[KK][128], sv[KK][128];
    __shared__ float sc[KK][KK + 2];
    __shared__ float wcol[KK];

    for (int hd = 0; hd < 4; hd++) {
        for (int i = tid; i < KK * 128; i += 256) {
            int a = i >> 7, d = i & 127;
            size_t base = (size_t)(p * KK + a) * (3 * HH) + hd * 128 + d;
            sq[a][d] = g_qkv[base];
            sk[a][d] = g_qkv[base + HH];
            sv[a][d] = g_qkv[base + 2 * HH];
        }
        __syncthreads();
        if (tid < KK * KK) {
            int a = tid / KK, b = tid % KK;
            float s = 0.f;
#pragma unroll 8
            for (int d = 0; d < 128; d++) s += sq[a][d] * sk[b][d];
            sc[a][b] = s * 0.08838834764831845f;
        }
        __syncthreads();
        if (tid < KK) {
            int a = tid;
            float mx = -1e30f;
            for (int b = 0; b < KK; b++) mx = fmaxf(mx, sc[a][b]);
            float e[KK], sum = 0.f;
            for (int b = 0; b < KK; b++) { e[b] = expf(sc[a][b] - mx); sum += e[b]; }
            float inv = 1.f / sum;
            for (int b = 0; b < KK; b++) sc[a][b] = e[b] * inv;
        }
        __syncthreads();
        if (tid < KK) {
            int b = tid;
            float s = 0.f;
            for (int a = 0; a < KK; a++) s += sc[a][b];
            wcol[b] = s * 0.1f;
        }
        __syncthreads();
        if (tid < 128) {
            int d = tid;
            float s = 0.f;
#pragma unroll
            for (int b = 0; b < KK; b++) s += wcol[b] * sv[b][d];
            g_ctxmean[(size_t)p * HH + hd * 128 + d] = tf32r(s);
        }
        __syncthreads();
    }
}

// ---------------- launch --------------------------------------------------
extern "C" void kernel_launch(void* const* d_in, const int* in_sizes, int n_in,
                              void* d_out, int out_size) {
    const int*   rel_idx     = (const int*)d_in[0];
    const int*   ent_idx     = (const int*)d_in[1];
    const int*   path_lens   = (const int*)d_in[2];
    const float* rel_table   = (const float*)d_in[3];
    const float* ent_table   = (const float*)d_in[4];
    const float* kg_proj_w   = (const float*)d_in[5];
    const float* kg_proj_b   = (const float*)d_in[6];
    const float* w_ih        = (const float*)d_in[7];
    const float* w_hh        = (const float*)d_in[8];
    const float* b_ih        = (const float*)d_in[9];
    const float* b_hh        = (const float*)d_in[10];
    const float* attn_in_w   = (const float*)d_in[11];
    const float* attn_in_b   = (const float*)d_in[12];
    const float* attn_out_w  = (const float*)d_in[13];
    const float* attn_out_b  = (const float*)d_in[14];
    const float* path_proj_w = (const float*)d_in[15];
    const float* path_proj_b = (const float*)d_in[16];
    float* out = (float*)d_out;

    float *pW12, *pRel, *pEnt, *pH0, *pH1, *pPemb, *pQkv, *pCtx, *pWc, *pBc2;
    float *pAiw, *pEntr, *pRelr, *pWihr, *pKgwT;
    int *pPerm, *pCnt, *pWmap;
    cudaGetSymbolAddress((void**)&pW12, g_W12);
    cudaGetSymbolAddress((void**)&pRel, g_rel_gate);
    cudaGetSymbolAddress((void**)&pEnt, g_ent_gate);
    cudaGetSymbolAddress((void**)&pH0, g_h0);
    cudaGetSymbolAddress((void**)&pH1, g_h1);
    cudaGetSymbolAddress((void**)&pPemb, g_pemb);
    cudaGetSymbolAddress((void**)&pQkv, g_qkv);
    cudaGetSymbolAddress((void**)&pCtx, g_ctxmean);
    cudaGetSymbolAddress((void**)&pWc, g_Wc);
    cudaGetSymbolAddress((void**)&pBc2, g_bc2);
    cudaGetSymbolAddress((void**)&pAiw, g_aiw);
    cudaGetSymbolAddress((void**)&pEntr, g_entr);
    cudaGetSymbolAddress((void**)&pRelr, g_relr);
    cudaGetSymbolAddress((void**)&pWihr, g_wihr);
    cudaGetSymbolAddress((void**)&pKgwT, g_kgwT);
    cudaGetSymbolAddress((void**)&pPerm, g_perm);
    cudaGetSymbolAddress((void**)&pCnt, g_cnt);
    cudaGetSymbolAddress((void**)&pWmap, g_wmap);

    cudaFuncSetAttribute(mma_gemm, cudaFuncAttributeMaxDynamicSharedMemorySize, MG_SMEM);
    cudaFuncSetAttribute(mma_gemm_lstm, cudaFuncAttributeMaxDynamicSharedMemorySize, MGL_SMEM);

    // --- operand prep: one fused rounding pass + transpose + row map ---
    const int n4_wih = G4 * 2 * HH / 4;       // 524288
    const int n4_ent = NENT * EE / 4;         // 640000
    const int n4_rel = NREL * EE / 4;         // 12800
    const int n4_aiw = 3 * HH * HH / 4;       // 196608
    const int n4_tot = n4_wih + n4_ent + n4_rel + n4_aiw;
    round4_kernel<<<(n4_tot + 255) / 256, 256>>>(
        w_ih, pWihr, n4_wih, ent_table, pEntr, n4_ent,
        rel_table, pRelr, n4_rel, attn_in_w, pAiw, n4_aiw);
    kgwT_kernel<<<(EE * HH + 255) / 256, 256>>>(kg_proj_w);
    wmap_kernel<<<(2 * G4 + 255) / 256, 256>>>();

    // --- W1|W2 fold as ONE tf32 GEMM: [4096,512] view of w_ih, scatter rows ---
    mma_gemm<<<dim3(EE / 128, 2 * G4 / 128), 256, MG_SMEM>>>(
        pWihr, HH, pKgwT, nullptr, pW12, EE, 2 * G4, HH, nullptr, pWmap);

    // --- per-entity gate tables (interleaved cols via interleaved W rows) ---
    mma_gemm<<<dim3(G4 / 128, (NENT + 127) / 128), 256, MG_SMEM>>>(
        pEntr, EE, pW12 + (size_t)G4 * EE, nullptr, pEnt, G4, NENT, EE, nullptr, nullptr);
    mma_gemm<<<dim3(G4 / 128, (NREL + 127) / 128), 256, MG_SMEM>>>(
        pRelr, EE, pW12, nullptr, pRel, G4, NREL, EE, nullptr, nullptr);

    // --- counting sort by path length (descending) ---
    sort_init<<<1, 32>>>();
    sort_count<<<(NPK + 255) / 256, 256>>>(path_lens);
    sort_prefix<<<1, 1>>>();
    sort_scatter<<<(NPK + 255) / 256, 256>>>(path_lens);

    reorder_whr_kernel<<<G4, 128>>>(w_hh);
    biasc_kernel<<<G4, 128>>>(kg_proj_b, w_ih, b_ih, b_hh);

    // folded output projection: Wc = ppw@aow (fp32, rounded out), bc2 fold
    gemm_nn_small<<<dim3(HH / BN, HH / BM), TPB>>>(path_proj_w, attn_out_w, pWc,
                                                   HH, HH, HH, HH, HH, HH);
    biasfold_kernel<<<HH, 128>>>(path_proj_w, attn_out_b, path_proj_b);

    // --- LSTM: step0 gather; steps 1,2 fused GEMM+cell on compacted prefix ---
    step0_kernel<<<NPK, 128>>>(rel_idx, ent_idx, path_lens, pPerm);
    mma_gemm_lstm<<<dim3(G4 / 128, NPK / 128), 256, MGL_SMEM>>>(
        pH0, pH1, rel_idx, ent_idx, path_lens, pPerm, pCnt + 1, 1);
    mma_gemm_lstm<<<dim3(G4 / 128, NPK / 128), 256, MGL_SMEM>>>(
        pH1, pH0, rel_idx, ent_idx, path_lens, pPerm, pCnt + 0, 2);

    // --- QKV projection (compacted pemb rows; scatter to original layout) ---
    mma_gemm<<<dim3(3 * HH / 128, NPK / 128), 256, MG_SMEM>>>(
        pPemb, HH, pAiw, attn_in_b, pQkv, 3 * HH, NPK, HH, pCnt + 2, pPerm);
    qkv_fill_kernel<<<NPK, 128>>>(attn_in_b, pPerm, pCnt + 2);

    // --- attention with folded mean -> ctxmean ---
    attn_kernel<<<PP, 256>>>();

    // --- single folded output GEMM: out = ctxmean @ Wc^T + bc2 ---
    mma_gemm<<<dim3(HH / 128, PP / 128), 256, MG_SMEM>>>(
        pCtx, HH, pWc, pBc2, out, HH, PP, HH, nullptr, nullptr);
}